// round 1
// baseline (speedup 1.0000x reference)
#include <cuda_runtime.h>
#include <cuda_bf16.h>
#include <cstdint>

#define NN 50000
#define EE 800000
#define FD 256          // H*HID
#define NEG 0.2f

// ---------------- scratch (device globals; no allocation allowed) ------------
__device__ float g_feat[(size_t)NN * FD];
__device__ float g_hA[(size_t)NN * FD];
__device__ float g_hB[(size_t)NN * FD];
__device__ float g_el[NN * 4];
__device__ float g_er[NN * 4];
__device__ float g_f4[NN * 8];
__device__ float g_r4[NN * 8];
__device__ int   g_cnt[NN];
__device__ int   g_rowptr[NN + 1];
__device__ int   g_cur[NN];
__device__ int   g_csrc[EE];

// ---------------- CSR build --------------------------------------------------
__global__ void k_zero_cnt(int* cnt) {
    int i = blockIdx.x * blockDim.x + threadIdx.x;
    if (i < NN) cnt[i] = 0;
}

__global__ void k_histo(const int* __restrict__ dst, int* __restrict__ cnt, int E) {
    for (int i = blockIdx.x * blockDim.x + threadIdx.x; i < E; i += gridDim.x * blockDim.x)
        atomicAdd(&cnt[dst[i]], 1);
}

// single-block scan over NN counts -> exclusive prefix in rowptr + cur
__global__ void k_scan(const int* __restrict__ cnt, int* __restrict__ rowptr,
                       int* __restrict__ cur) {
    __shared__ int sh[1024];
    __shared__ int carry;
    int tid = threadIdx.x;
    if (tid == 0) carry = 0;
    __syncthreads();
    for (int base = 0; base < NN; base += 1024) {
        int i = base + tid;
        int v = (i < NN) ? cnt[i] : 0;
        sh[tid] = v;
        __syncthreads();
        #pragma unroll
        for (int o = 1; o < 1024; o <<= 1) {
            int t = (tid >= o) ? sh[tid - o] : 0;
            __syncthreads();
            sh[tid] += t;
            __syncthreads();
        }
        int excl = sh[tid] - v;
        int c = carry;
        if (i < NN) { rowptr[i] = c + excl; cur[i] = c + excl; }
        int tot = sh[1023];
        __syncthreads();
        if (tid == 0) carry = c + tot;
        __syncthreads();
    }
    if (tid == 0) rowptr[NN] = carry;
}

__global__ void k_scatter(const int* __restrict__ src, const int* __restrict__ dst,
                          int* __restrict__ cur, int* __restrict__ csrc, int E) {
    for (int i = blockIdx.x * blockDim.x + threadIdx.x; i < E; i += gridDim.x * blockDim.x) {
        int d = dst[i];
        int p = atomicAdd(&cur[d], 1);
        csrc[p] = src[i];
    }
}

// ---------------- SGEMM: C[M,Nc] = A[M,K] @ B[Nc,K]^T  (fp32) ----------------
// BM=128, BN=64, BK=16, 256 threads, each thread 8x4 outputs.
__global__ void k_sgemm_nt(const float* __restrict__ A, const float* __restrict__ B,
                           float* __restrict__ C, int M, int Nc, int K) {
    __shared__ float As[16][132];  // [k][m], padded
    __shared__ float Bs[16][68];   // [k][n], padded
    const int bm = blockIdx.y * 128, bn = blockIdx.x * 64;
    const int tid = threadIdx.x;
    const int tr = tid >> 4, tc = tid & 15;       // 16x16 thread grid
    const int row0 = tr * 8, col0 = tc * 4;
    const int lr = tid >> 2, lc = tid & 3;        // loader mapping

    float acc[8][4];
    #pragma unroll
    for (int i = 0; i < 8; i++)
        #pragma unroll
        for (int j = 0; j < 4; j++) acc[i][j] = 0.f;

    for (int kt = 0; kt < K; kt += 16) {
        int r0i = bm + lr, r1i = bm + lr + 64;
        float4 a0 = make_float4(0.f, 0.f, 0.f, 0.f), a1 = a0;
        if (r0i < M) a0 = *(const float4*)&A[(size_t)r0i * K + kt + lc * 4];
        if (r1i < M) a1 = *(const float4*)&A[(size_t)r1i * K + kt + lc * 4];
        float4 b0 = *(const float4*)&B[(size_t)(bn + lr) * K + kt + lc * 4];
        __syncthreads();
        As[lc * 4 + 0][lr] = a0.x;  As[lc * 4 + 1][lr] = a0.y;
        As[lc * 4 + 2][lr] = a0.z;  As[lc * 4 + 3][lr] = a0.w;
        As[lc * 4 + 0][lr + 64] = a1.x;  As[lc * 4 + 1][lr + 64] = a1.y;
        As[lc * 4 + 2][lr + 64] = a1.z;  As[lc * 4 + 3][lr + 64] = a1.w;
        Bs[lc * 4 + 0][lr] = b0.x;  Bs[lc * 4 + 1][lr] = b0.y;
        Bs[lc * 4 + 2][lr] = b0.z;  Bs[lc * 4 + 3][lr] = b0.w;
        __syncthreads();
        #pragma unroll
        for (int kk = 0; kk < 16; kk++) {
            const float4 av0 = *(const float4*)&As[kk][row0];
            const float4 av1 = *(const float4*)&As[kk][row0 + 4];
            const float4 bv  = *(const float4*)&Bs[kk][col0];
            float a[8] = {av0.x, av0.y, av0.z, av0.w, av1.x, av1.y, av1.z, av1.w};
            float b[4] = {bv.x, bv.y, bv.z, bv.w};
            #pragma unroll
            for (int i = 0; i < 8; i++)
                #pragma unroll
                for (int j = 0; j < 4; j++)
                    acc[i][j] = fmaf(a[i], b[j], acc[i][j]);
        }
    }
    #pragma unroll
    for (int i = 0; i < 8; i++) {
        int r = bm + row0 + i;
        if (r < M) {
            float4 o = make_float4(acc[i][0], acc[i][1], acc[i][2], acc[i][3]);
            *(float4*)&C[(size_t)r * Nc + bn + col0] = o;
        }
    }
}

// ---------------- el/er per node (256-wide layers) ---------------------------
__global__ void k_elr(const float* __restrict__ feat, const float* __restrict__ al,
                      const float* __restrict__ ar, float* __restrict__ el,
                      float* __restrict__ er) {
    int n = blockIdx.x;
    int ch = threadIdx.x;                 // 256
    float f = feat[(size_t)n * FD + ch];
    float pl = f * al[ch];
    float pr = f * ar[ch];
    #pragma unroll
    for (int o = 16; o > 0; o >>= 1) {
        pl += __shfl_down_sync(0xffffffffu, pl, o);
        pr += __shfl_down_sync(0xffffffffu, pr, o);
    }
    __shared__ float sl[8], sr[8];
    int w = ch >> 5;
    if ((ch & 31) == 0) { sl[w] = pl; sr[w] = pr; }
    __syncthreads();
    if (ch < 4) {
        el[n * 4 + ch] = sl[2 * ch] + sl[2 * ch + 1];
        er[n * 4 + ch] = sr[2 * ch] + sr[2 * ch + 1];
    }
}

// ---------------- fused edge aggregation (256-wide) --------------------------
// One block per dst node; thread = output channel. Computes softmax weights in
// shared, gathers feat[src], accumulates, then residual+bias+ELU.
#define CHUNK 32
__global__ void k_edge_agg(const float* __restrict__ feat, const float* __restrict__ el,
                           const float* __restrict__ er, const int* __restrict__ rowptr,
                           const int* __restrict__ csrc, const float* __restrict__ hprev,
                           const float* __restrict__ bias, float* __restrict__ hout) {
    int n = blockIdx.x;
    int ch = threadIdx.x;                 // 0..255
    int hh = ch >> 6;
    __shared__ float sw[CHUNK * 4];
    __shared__ int   ssrc[CHUNK];
    __shared__ float serd[4];
    __shared__ float sden[4];
    int beg = rowptr[n], end = rowptr[n + 1];
    if (ch < 4) { serd[ch] = er[n * 4 + ch]; sden[ch] = 0.f; }
    float acc = 0.f;
    for (int base = beg; base < end; base += CHUNK) {
        int cnt = min(CHUNK, end - base);
        __syncthreads();                  // protects ssrc/sw reuse; serd on iter 0
        if (ch < cnt) ssrc[ch] = csrc[base + ch];
        __syncthreads();
        if (ch < cnt * 4) {
            int e = ch >> 2, h = ch & 3;
            float xv = el[ssrc[e] * 4 + h] + serd[h];
            xv = xv > 0.f ? xv : NEG * xv;
            float w = expf(xv);
            sw[e * 4 + h] = w;
            atomicAdd(&sden[h], w);
        }
        __syncthreads();
        int e = 0;
        for (; e + 4 <= cnt; e += 4) {
            float f0 = feat[(size_t)ssrc[e + 0] * FD + ch];
            float f1 = feat[(size_t)ssrc[e + 1] * FD + ch];
            float f2 = feat[(size_t)ssrc[e + 2] * FD + ch];
            float f3 = feat[(size_t)ssrc[e + 3] * FD + ch];
            acc = fmaf(f0, sw[(e + 0) * 4 + hh], acc);
            acc = fmaf(f1, sw[(e + 1) * 4 + hh], acc);
            acc = fmaf(f2, sw[(e + 2) * 4 + hh], acc);
            acc = fmaf(f3, sw[(e + 3) * 4 + hh], acc);
        }
        for (; e < cnt; e++)
            acc = fmaf(feat[(size_t)ssrc[e] * FD + ch], sw[e * 4 + hh], acc);
    }
    float v = (end > beg) ? acc / sden[hh] : 0.f;
    if (hprev) v += hprev[(size_t)n * FD + ch];
    v += bias[ch];
    v = v > 0.f ? v : expm1f(v);          // ELU
    hout[(size_t)n * FD + ch] = v;
}

// ---------------- layer-4 projection: feat4 & fc-residual --------------------
// warp per node; 8 outputs for W4 and 8 for resW4, K=256.
__global__ void k_l4_proj(const float* __restrict__ h, const float* __restrict__ W4,
                          const float* __restrict__ rW4, float* __restrict__ f4,
                          float* __restrict__ r4) {
    int n = blockIdx.x * 8 + (threadIdx.x >> 5);
    int lane = threadIdx.x & 31;
    if (n >= NN) return;
    float acc[16];
    #pragma unroll
    for (int o = 0; o < 16; o++) acc[o] = 0.f;
    const float* hr = h + (size_t)n * FD;
    for (int k = lane; k < FD; k += 32) {
        float hv = hr[k];
        #pragma unroll
        for (int o = 0; o < 8; o++) acc[o]     = fmaf(hv, W4[o * FD + k], acc[o]);
        #pragma unroll
        for (int o = 0; o < 8; o++) acc[8 + o] = fmaf(hv, rW4[o * FD + k], acc[8 + o]);
    }
    #pragma unroll
    for (int o = 0; o < 16; o++)
        #pragma unroll
        for (int off = 16; off > 0; off >>= 1)
            acc[o] += __shfl_xor_sync(0xffffffffu, acc[o], off);
    if (lane < 8) {
        f4[n * 8 + lane] = acc[lane];
        r4[n * 8 + lane] = acc[8 + lane];
    }
}

__global__ void k_elr4(const float* __restrict__ f4, const float* __restrict__ al4,
                       const float* __restrict__ ar4, float* __restrict__ el,
                       float* __restrict__ er) {
    int n = blockIdx.x * blockDim.x + threadIdx.x;
    if (n >= NN) return;
    float4 f0 = ((const float4*)f4)[n * 2];
    float4 f1 = ((const float4*)f4)[n * 2 + 1];
    el[n * 4 + 0] = f0.x * al4[0] + f0.y * al4[1];
    el[n * 4 + 1] = f0.z * al4[2] + f0.w * al4[3];
    el[n * 4 + 2] = f1.x * al4[4] + f1.y * al4[5];
    el[n * 4 + 3] = f1.z * al4[6] + f1.w * al4[7];
    er[n * 4 + 0] = f0.x * ar4[0] + f0.y * ar4[1];
    er[n * 4 + 1] = f0.z * ar4[2] + f0.w * ar4[3];
    er[n * 4 + 2] = f1.x * ar4[4] + f1.y * ar4[5];
    er[n * 4 + 3] = f1.z * ar4[6] + f1.w * ar4[7];
}

// ---------------- layer-4 edge agg + softmax + head-mean ---------------------
// warp per node, 8 channels (H=4, C=2).
__global__ void k_l4_edge(const float* __restrict__ f4, const float* __restrict__ el,
                          const float* __restrict__ er, const int* __restrict__ rowptr,
                          const int* __restrict__ csrc, const float* __restrict__ r4,
                          const float* __restrict__ b4, float* __restrict__ out) {
    int n = blockIdx.x * 8 + (threadIdx.x >> 5);
    int lane = threadIdx.x & 31;
    if (n >= NN) return;
    int beg = rowptr[n], end = rowptr[n + 1];
    float4 erd = ((const float4*)er)[n];
    float acc[8] = {0, 0, 0, 0, 0, 0, 0, 0};
    float den[4] = {0, 0, 0, 0};
    for (int e = beg + lane; e < end; e += 32) {
        int s = csrc[e];
        float4 le = ((const float4*)el)[s];
        float x0 = le.x + erd.x; x0 = x0 > 0.f ? x0 : NEG * x0;
        float x1 = le.y + erd.y; x1 = x1 > 0.f ? x1 : NEG * x1;
        float x2 = le.z + erd.z; x2 = x2 > 0.f ? x2 : NEG * x2;
        float x3 = le.w + erd.w; x3 = x3 > 0.f ? x3 : NEG * x3;
        float w0 = expf(x0), w1 = expf(x1), w2 = expf(x2), w3 = expf(x3);
        den[0] += w0; den[1] += w1; den[2] += w2; den[3] += w3;
        float4 f0 = ((const float4*)f4)[s * 2];
        float4 f1 = ((const float4*)f4)[s * 2 + 1];
        acc[0] = fmaf(f0.x, w0, acc[0]);  acc[1] = fmaf(f0.y, w0, acc[1]);
        acc[2] = fmaf(f0.z, w1, acc[2]);  acc[3] = fmaf(f0.w, w1, acc[3]);
        acc[4] = fmaf(f1.x, w2, acc[4]);  acc[5] = fmaf(f1.y, w2, acc[5]);
        acc[6] = fmaf(f1.z, w3, acc[6]);  acc[7] = fmaf(f1.w, w3, acc[7]);
    }
    #pragma unroll
    for (int off = 16; off > 0; off >>= 1) {
        #pragma unroll
        for (int o = 0; o < 8; o++) acc[o] += __shfl_xor_sync(0xffffffffu, acc[o], off);
        #pragma unroll
        for (int h = 0; h < 4; h++) den[h] += __shfl_xor_sync(0xffffffffu, den[h], off);
    }
    if (lane == 0) {
        bool has = end > beg;
        float o0 = 0.f, o1 = 0.f;
        #pragma unroll
        for (int h = 0; h < 4; h++) {
            float r0 = has ? acc[2 * h] / den[h] : 0.f;
            float r1 = has ? acc[2 * h + 1] / den[h] : 0.f;
            r0 += r4[n * 8 + 2 * h] + b4[2 * h];
            r1 += r4[n * 8 + 2 * h + 1] + b4[2 * h + 1];
            float m = fmaxf(r0, r1);
            float e0 = expf(r0 - m), e1 = expf(r1 - m);
            float s = e0 + e1;
            o0 += e0 / s;
            o1 += e1 / s;
        }
        out[n * 2 + 0] = o0 * 0.25f;
        out[n * 2 + 1] = o1 * 0.25f;
    }
}

// ---------------- host launcher ----------------------------------------------
extern "C" void kernel_launch(void* const* d_in, const int* in_sizes, int n_in,
                              void* d_out, int out_size) {
    const float* x     = (const float*)d_in[0];
    const int*   src   = (const int*)  d_in[1];
    const int*   dst   = (const int*)  d_in[2];
    const float* W1    = (const float*)d_in[3];
    const float* al1   = (const float*)d_in[4];
    const float* ar1   = (const float*)d_in[5];
    const float* b1    = (const float*)d_in[6];
    const float* W2    = (const float*)d_in[7];
    const float* al2   = (const float*)d_in[8];
    const float* ar2   = (const float*)d_in[9];
    const float* b2    = (const float*)d_in[10];
    const float* W3    = (const float*)d_in[11];
    const float* al3   = (const float*)d_in[12];
    const float* ar3   = (const float*)d_in[13];
    const float* b3    = (const float*)d_in[14];
    const float* W4    = (const float*)d_in[15];
    const float* al4   = (const float*)d_in[16];
    const float* ar4   = (const float*)d_in[17];
    const float* b4    = (const float*)d_in[18];
    const float* resW4 = (const float*)d_in[19];
    float* out = (float*)d_out;
    const int E = in_sizes[1];

    float *feat, *hA, *hB, *el, *er, *f4, *r4;
    int *cnt, *rowptr, *cur, *csrc;
    cudaGetSymbolAddress((void**)&feat,   g_feat);
    cudaGetSymbolAddress((void**)&hA,     g_hA);
    cudaGetSymbolAddress((void**)&hB,     g_hB);
    cudaGetSymbolAddress((void**)&el,     g_el);
    cudaGetSymbolAddress((void**)&er,     g_er);
    cudaGetSymbolAddress((void**)&f4,     g_f4);
    cudaGetSymbolAddress((void**)&r4,     g_r4);
    cudaGetSymbolAddress((void**)&cnt,    g_cnt);
    cudaGetSymbolAddress((void**)&rowptr, g_rowptr);
    cudaGetSymbolAddress((void**)&cur,    g_cur);
    cudaGetSymbolAddress((void**)&csrc,   g_csrc);

    // ---- CSR by dst (fixed graph, rebuilt deterministically each call) ----
    k_zero_cnt<<<(NN + 255) / 256, 256>>>(cnt);
    k_histo<<<512, 256>>>(dst, cnt, E);
    k_scan<<<1, 1024>>>(cnt, rowptr, cur);
    k_scatter<<<512, 256>>>(src, dst, cur, csrc, E);

    dim3 gemm_grid(FD / 64, (NN + 127) / 128);

    // ---- layer 1: IN=128 -> (4,64), no residual, ELU ----
    k_sgemm_nt<<<gemm_grid, 256>>>(x, W1, feat, NN, FD, 128);
    k_elr<<<NN, 256>>>(feat, al1, ar1, el, er);
    k_edge_agg<<<NN, 256>>>(feat, el, er, rowptr, csrc, nullptr, b1, hA);

    // ---- layer 2: 256 -> (4,64), identity residual, ELU ----
    k_sgemm_nt<<<gemm_grid, 256>>>(hA, W2, feat, NN, FD, FD);
    k_elr<<<NN, 256>>>(feat, al2, ar2, el, er);
    k_edge_agg<<<NN, 256>>>(feat, el, er, rowptr, csrc, hA, b2, hB);

    // ---- layer 3 ----
    k_sgemm_nt<<<gemm_grid, 256>>>(hB, W3, feat, NN, FD, FD);
    k_elr<<<NN, 256>>>(feat, al3, ar3, el, er);
    k_edge_agg<<<NN, 256>>>(feat, el, er, rowptr, csrc, hB, b3, hA);

    // ---- layer 4: 256 -> (4,2), fc residual, softmax, head-mean ----
    k_l4_proj<<<(NN + 7) / 8, 256>>>(hA, W4, resW4, f4, r4);
    k_elr4<<<(NN + 255) / 256, 256>>>(f4, al4, ar4, el, er);
    k_l4_edge<<<(NN + 7) / 8, 256>>>(f4, el, er, rowptr, csrc, r4, b4, out);
}

// round 2
// speedup vs baseline: 1.5664x; 1.5664x over previous
#include <cuda_runtime.h>
#include <cuda_bf16.h>
#include <cstdint>

#define NN 50000
#define EE 800000
#define FD 256          // H*HID
#define NEG 0.2f
#define NB 49           // ceil(NN/1024)

// ---------------- scratch (device globals; no allocation allowed) ------------
__device__ float g_feat[(size_t)NN * FD];
__device__ float g_hA[(size_t)NN * FD];
__device__ float g_hB[(size_t)NN * FD];
__device__ float g_el[NN * 4];
__device__ float g_er[NN * 4];
__device__ float g_f4[NN * 8];
__device__ float g_r4[NN * 8];
__device__ int   g_cnt[NN];
__device__ int   g_rowptr[NN + 1];
__device__ int   g_cur[NN];
__device__ int   g_csrc[EE];
__device__ int   g_bsum[64];

// ---------------- CSR build --------------------------------------------------
__global__ void k_zero_cnt(int* cnt) {
    int i = blockIdx.x * blockDim.x + threadIdx.x;
    if (i < NN) cnt[i] = 0;
}

__global__ void k_histo(const int* __restrict__ dst, int* __restrict__ cnt, int E) {
    for (int i = blockIdx.x * blockDim.x + threadIdx.x; i < E; i += gridDim.x * blockDim.x)
        atomicAdd(&cnt[dst[i]], 1);
}

// hierarchical scan: block sums -> tiny scan -> per-block scan
__global__ void k_scan_part(const int* __restrict__ cnt) {
    __shared__ int sh[1024];
    int i = blockIdx.x * 1024 + threadIdx.x;
    sh[threadIdx.x] = (i < NN) ? cnt[i] : 0;
    __syncthreads();
    for (int o = 512; o > 0; o >>= 1) {
        if (threadIdx.x < o) sh[threadIdx.x] += sh[threadIdx.x + o];
        __syncthreads();
    }
    if (threadIdx.x == 0) g_bsum[blockIdx.x] = sh[0];
}

__global__ void k_scan_small(int* rowptr) {
    int acc = 0;
    for (int b = 0; b < NB; b++) { int v = g_bsum[b]; g_bsum[b] = acc; acc += v; }
    rowptr[NN] = acc;
}

__global__ void k_scan_final(const int* __restrict__ cnt, int* __restrict__ rowptr,
                             int* __restrict__ cur) {
    __shared__ int sh[1024];
    int tid = threadIdx.x;
    int i = blockIdx.x * 1024 + tid;
    int v = (i < NN) ? cnt[i] : 0;
    sh[tid] = v;
    __syncthreads();
    #pragma unroll
    for (int o = 1; o < 1024; o <<= 1) {
        int t = (tid >= o) ? sh[tid - o] : 0;
        __syncthreads();
        sh[tid] += t;
        __syncthreads();
    }
    if (i < NN) { int ex = g_bsum[blockIdx.x] + sh[tid] - v; rowptr[i] = ex; cur[i] = ex; }
}

__global__ void k_scatter(const int* __restrict__ src, const int* __restrict__ dst,
                          int* __restrict__ cur, int* __restrict__ csrc, int E) {
    for (int i = blockIdx.x * blockDim.x + threadIdx.x; i < E; i += gridDim.x * blockDim.x) {
        int d = dst[i];
        int p = atomicAdd(&cur[d], 1);
        csrc[p] = src[i];
    }
}

// ---------------- tf32 tensor-core GEMM: C[M,Nc] = A[M,K] @ B[Nc,K]^T --------
// BM=128, BN=64, BK=32; 256 threads = 8 warps (4 along M x 2 along N),
// warp tile 32x32 via mma.sync.m16n8k8 tf32, fp32 accumulate.
#define BM 128
#define BN 64
#define BK 32

__device__ __forceinline__ float to_tf32(float x) {
    uint32_t u;
    asm("cvt.rna.tf32.f32 %0, %1;" : "=r"(u) : "f"(x));
    return __uint_as_float(u);
}

__device__ __forceinline__ void mma_tf32(float (&d)[4], const uint32_t (&a)[4],
                                         const uint32_t (&b)[2]) {
    asm volatile(
        "mma.sync.aligned.m16n8k8.row.col.f32.tf32.tf32.f32 "
        "{%0,%1,%2,%3},{%4,%5,%6,%7},{%8,%9},{%0,%1,%2,%3};"
        : "+f"(d[0]), "+f"(d[1]), "+f"(d[2]), "+f"(d[3])
        : "r"(a[0]), "r"(a[1]), "r"(a[2]), "r"(a[3]), "r"(b[0]), "r"(b[1]));
}

__global__ void __launch_bounds__(256) k_gemm_tf32(const float* __restrict__ A,
                                                   const float* __restrict__ B,
                                                   float* __restrict__ C,
                                                   int M, int Nc, int K) {
    __shared__ float As[BK][BM + 8];
    __shared__ float Bs[BK][BN + 8];
    const int bm = blockIdx.y * BM, bn = blockIdx.x * BN;
    const int tid = threadIdx.x;
    const int warp = tid >> 5, lane = tid & 31;
    const int wm = warp & 3, wn = warp >> 2;
    const int r = lane >> 2, c = lane & 3;
    // loaders
    const int ar = tid >> 1, ahalf = (tid & 1) * 16;    // A: 4 float4 each
    const int br = tid >> 2, bq = (tid & 3) * 8;        // B: 2 float4 each

    float acc[2][4][4];
    #pragma unroll
    for (int mt = 0; mt < 2; mt++)
        #pragma unroll
        for (int nt = 0; nt < 4; nt++)
            #pragma unroll
            for (int i = 0; i < 4; i++) acc[mt][nt][i] = 0.f;

    const bool arow_ok = (bm + ar) < M;
    for (int kt = 0; kt < K; kt += BK) {
        float4 aR[4], bR[2];
        #pragma unroll
        for (int j = 0; j < 4; j++) {
            aR[j] = arow_ok ? *(const float4*)&A[(size_t)(bm + ar) * K + kt + ahalf + 4 * j]
                            : make_float4(0.f, 0.f, 0.f, 0.f);
        }
        #pragma unroll
        for (int j = 0; j < 2; j++)
            bR[j] = *(const float4*)&B[(size_t)(bn + br) * K + kt + bq + 4 * j];
        __syncthreads();
        #pragma unroll
        for (int j = 0; j < 4; j++) {
            As[ahalf + 4 * j + 0][ar] = to_tf32(aR[j].x);
            As[ahalf + 4 * j + 1][ar] = to_tf32(aR[j].y);
            As[ahalf + 4 * j + 2][ar] = to_tf32(aR[j].z);
            As[ahalf + 4 * j + 3][ar] = to_tf32(aR[j].w);
        }
        #pragma unroll
        for (int j = 0; j < 2; j++) {
            Bs[bq + 4 * j + 0][br] = to_tf32(bR[j].x);
            Bs[bq + 4 * j + 1][br] = to_tf32(bR[j].y);
            Bs[bq + 4 * j + 2][br] = to_tf32(bR[j].z);
            Bs[bq + 4 * j + 3][br] = to_tf32(bR[j].w);
        }
        __syncthreads();
        #pragma unroll
        for (int kk = 0; kk < BK; kk += 8) {
            uint32_t af[2][4], bf[4][2];
            #pragma unroll
            for (int mt = 0; mt < 2; mt++) {
                int row0 = wm * 32 + mt * 16 + r;
                af[mt][0] = __float_as_uint(As[kk + c][row0]);
                af[mt][1] = __float_as_uint(As[kk + c][row0 + 8]);
                af[mt][2] = __float_as_uint(As[kk + c + 4][row0]);
                af[mt][3] = __float_as_uint(As[kk + c + 4][row0 + 8]);
            }
            #pragma unroll
            for (int nt = 0; nt < 4; nt++) {
                int col0 = wn * 32 + nt * 8 + r;
                bf[nt][0] = __float_as_uint(Bs[kk + c][col0]);
                bf[nt][1] = __float_as_uint(Bs[kk + c + 4][col0]);
            }
            #pragma unroll
            for (int mt = 0; mt < 2; mt++)
                #pragma unroll
                for (int nt = 0; nt < 4; nt++)
                    mma_tf32(acc[mt][nt], af[mt], bf[nt]);
        }
    }
    #pragma unroll
    for (int mt = 0; mt < 2; mt++) {
        #pragma unroll
        for (int nt = 0; nt < 4; nt++) {
            int row = bm + wm * 32 + mt * 16 + r;
            int col = bn + wn * 32 + nt * 8 + 2 * c;
            if (row < M)
                *(float2*)&C[(size_t)row * Nc + col] =
                    make_float2(acc[mt][nt][0], acc[mt][nt][1]);
            if (row + 8 < M)
                *(float2*)&C[(size_t)(row + 8) * Nc + col] =
                    make_float2(acc[mt][nt][2], acc[mt][nt][3]);
        }
    }
}

// ---------------- el/er per node (256-wide layers) ---------------------------
__global__ void k_elr(const float* __restrict__ feat, const float* __restrict__ al,
                      const float* __restrict__ ar, float* __restrict__ el,
                      float* __restrict__ er) {
    int n = blockIdx.x;
    int ch = threadIdx.x;                 // 256
    float f = feat[(size_t)n * FD + ch];
    float pl = f * al[ch];
    float pr = f * ar[ch];
    #pragma unroll
    for (int o = 16; o > 0; o >>= 1) {
        pl += __shfl_down_sync(0xffffffffu, pl, o);
        pr += __shfl_down_sync(0xffffffffu, pr, o);
    }
    __shared__ float sl[8], sr[8];
    int w = ch >> 5;
    if ((ch & 31) == 0) { sl[w] = pl; sr[w] = pr; }
    __syncthreads();
    if (ch < 4) {
        el[n * 4 + ch] = sl[2 * ch] + sl[2 * ch + 1];
        er[n * 4 + ch] = sr[2 * ch] + sr[2 * ch + 1];
    }
}

// ---------------- fused edge aggregation (64 threads/node, float4/thread) ----
#define ECH 16
__global__ void __launch_bounds__(64) k_edge_agg(
        const float4* __restrict__ feat4, const float4* __restrict__ el4,
        const float4* __restrict__ er4, const int* __restrict__ rowptr,
        const int* __restrict__ csrc, const float4* __restrict__ hprev4,
        const float4* __restrict__ bias4, float4* __restrict__ hout4) {
    int n = blockIdx.x;
    int t = threadIdx.x;                  // 0..63, channels 4t..4t+3
    int hh = t >> 4;                      // head of my 4 channels
    __shared__ int   ssrc[ECH];
    __shared__ float sw[ECH][4];
    __shared__ float sden[4];
    int beg = rowptr[n], end = rowptr[n + 1];
    if (t < 4) sden[t] = 0.f;
    float4 erd = make_float4(0.f, 0.f, 0.f, 0.f);
    if (t < ECH) erd = er4[n];
    float4 acc = make_float4(0.f, 0.f, 0.f, 0.f);
    float4 dl  = make_float4(0.f, 0.f, 0.f, 0.f);
    for (int base = beg; base < end; base += ECH) {
        int cnt = min(ECH, end - base);
        __syncthreads();
        if (t < cnt) {
            int s = csrc[base + t];
            ssrc[t] = s;
            float4 le = el4[s];
            float x0 = le.x + erd.x; x0 = x0 > 0.f ? x0 : NEG * x0;
            float x1 = le.y + erd.y; x1 = x1 > 0.f ? x1 : NEG * x1;
            float x2 = le.z + erd.z; x2 = x2 > 0.f ? x2 : NEG * x2;
            float x3 = le.w + erd.w; x3 = x3 > 0.f ? x3 : NEG * x3;
            float w0 = expf(x0), w1 = expf(x1), w2 = expf(x2), w3 = expf(x3);
            sw[t][0] = w0; sw[t][1] = w1; sw[t][2] = w2; sw[t][3] = w3;
            dl.x += w0; dl.y += w1; dl.z += w2; dl.w += w3;
        }
        __syncthreads();
        int e = 0;
        for (; e + 2 <= cnt; e += 2) {
            float4 f0 = feat4[(size_t)ssrc[e] * 64 + t];
            float4 f1 = feat4[(size_t)ssrc[e + 1] * 64 + t];
            float w0 = sw[e][hh], w1 = sw[e + 1][hh];
            acc.x = fmaf(f0.x, w0, acc.x); acc.y = fmaf(f0.y, w0, acc.y);
            acc.z = fmaf(f0.z, w0, acc.z); acc.w = fmaf(f0.w, w0, acc.w);
            acc.x = fmaf(f1.x, w1, acc.x); acc.y = fmaf(f1.y, w1, acc.y);
            acc.z = fmaf(f1.z, w1, acc.z); acc.w = fmaf(f1.w, w1, acc.w);
        }
        if (e < cnt) {
            float4 f0 = feat4[(size_t)ssrc[e] * 64 + t];
            float w0 = sw[e][hh];
            acc.x = fmaf(f0.x, w0, acc.x); acc.y = fmaf(f0.y, w0, acc.y);
            acc.z = fmaf(f0.z, w0, acc.z); acc.w = fmaf(f0.w, w0, acc.w);
        }
    }
    if (t < ECH) {
        atomicAdd(&sden[0], dl.x); atomicAdd(&sden[1], dl.y);
        atomicAdd(&sden[2], dl.z); atomicAdd(&sden[3], dl.w);
    }
    __syncthreads();
    float inv = (end > beg) ? 1.f / sden[hh] : 0.f;
    float4 v = make_float4(acc.x * inv, acc.y * inv, acc.z * inv, acc.w * inv);
    if (hprev4) {
        float4 p = hprev4[(size_t)n * 64 + t];
        v.x += p.x; v.y += p.y; v.z += p.z; v.w += p.w;
    }
    float4 b = bias4[t];
    v.x += b.x; v.y += b.y; v.z += b.z; v.w += b.w;
    v.x = v.x > 0.f ? v.x : expm1f(v.x);
    v.y = v.y > 0.f ? v.y : expm1f(v.y);
    v.z = v.z > 0.f ? v.z : expm1f(v.z);
    v.w = v.w > 0.f ? v.w : expm1f(v.w);
    hout4[(size_t)n * 64 + t] = v;
}

// ---------------- layer-4 projection: feat4 & fc-residual --------------------
__global__ void k_l4_proj(const float* __restrict__ h, const float* __restrict__ W4,
                          const float* __restrict__ rW4, float* __restrict__ f4,
                          float* __restrict__ r4) {
    int n = blockIdx.x * 8 + (threadIdx.x >> 5);
    int lane = threadIdx.x & 31;
    if (n >= NN) return;
    float acc[16];
    #pragma unroll
    for (int o = 0; o < 16; o++) acc[o] = 0.f;
    const float* hr = h + (size_t)n * FD;
    for (int k = lane; k < FD; k += 32) {
        float hv = hr[k];
        #pragma unroll
        for (int o = 0; o < 8; o++) acc[o]     = fmaf(hv, W4[o * FD + k], acc[o]);
        #pragma unroll
        for (int o = 0; o < 8; o++) acc[8 + o] = fmaf(hv, rW4[o * FD + k], acc[8 + o]);
    }
    #pragma unroll
    for (int o = 0; o < 16; o++)
        #pragma unroll
        for (int off = 16; off > 0; off >>= 1)
            acc[o] += __shfl_xor_sync(0xffffffffu, acc[o], off);
    if (lane < 8) {
        f4[n * 8 + lane] = acc[lane];
        r4[n * 8 + lane] = acc[8 + lane];
    }
}

__global__ void k_elr4(const float* __restrict__ f4, const float* __restrict__ al4,
                       const float* __restrict__ ar4, float* __restrict__ el,
                       float* __restrict__ er) {
    int n = blockIdx.x * blockDim.x + threadIdx.x;
    if (n >= NN) return;
    float4 f0 = ((const float4*)f4)[n * 2];
    float4 f1 = ((const float4*)f4)[n * 2 + 1];
    el[n * 4 + 0] = f0.x * al4[0] + f0.y * al4[1];
    el[n * 4 + 1] = f0.z * al4[2] + f0.w * al4[3];
    el[n * 4 + 2] = f1.x * al4[4] + f1.y * al4[5];
    el[n * 4 + 3] = f1.z * al4[6] + f1.w * al4[7];
    er[n * 4 + 0] = f0.x * ar4[0] + f0.y * ar4[1];
    er[n * 4 + 1] = f0.z * ar4[2] + f0.w * ar4[3];
    er[n * 4 + 2] = f1.x * ar4[4] + f1.y * ar4[5];
    er[n * 4 + 3] = f1.z * ar4[6] + f1.w * ar4[7];
}

// ---------------- layer-4 edge agg + softmax + head-mean ---------------------
__global__ void k_l4_edge(const float* __restrict__ f4, const float* __restrict__ el,
                          const float* __restrict__ er, const int* __restrict__ rowptr,
                          const int* __restrict__ csrc, const float* __restrict__ r4,
                          const float* __restrict__ b4, float* __restrict__ out) {
    int n = blockIdx.x * 8 + (threadIdx.x >> 5);
    int lane = threadIdx.x & 31;
    if (n >= NN) return;
    int beg = rowptr[n], end = rowptr[n + 1];
    float4 erd = ((const float4*)er)[n];
    float acc[8] = {0, 0, 0, 0, 0, 0, 0, 0};
    float den[4] = {0, 0, 0, 0};
    for (int e = beg + lane; e < end; e += 32) {
        int s = csrc[e];
        float4 le = ((const float4*)el)[s];
        float x0 = le.x + erd.x; x0 = x0 > 0.f ? x0 : NEG * x0;
        float x1 = le.y + erd.y; x1 = x1 > 0.f ? x1 : NEG * x1;
        float x2 = le.z + erd.z; x2 = x2 > 0.f ? x2 : NEG * x2;
        float x3 = le.w + erd.w; x3 = x3 > 0.f ? x3 : NEG * x3;
        float w0 = expf(x0), w1 = expf(x1), w2 = expf(x2), w3 = expf(x3);
        den[0] += w0; den[1] += w1; den[2] += w2; den[3] += w3;
        float4 f0 = ((const float4*)f4)[s * 2];
        float4 f1 = ((const float4*)f4)[s * 2 + 1];
        acc[0] = fmaf(f0.x, w0, acc[0]);  acc[1] = fmaf(f0.y, w0, acc[1]);
        acc[2] = fmaf(f0.z, w1, acc[2]);  acc[3] = fmaf(f0.w, w1, acc[3]);
        acc[4] = fmaf(f1.x, w2, acc[4]);  acc[5] = fmaf(f1.y, w2, acc[5]);
        acc[6] = fmaf(f1.z, w3, acc[6]);  acc[7] = fmaf(f1.w, w3, acc[7]);
    }
    #pragma unroll
    for (int off = 16; off > 0; off >>= 1) {
        #pragma unroll
        for (int o = 0; o < 8; o++) acc[o] += __shfl_xor_sync(0xffffffffu, acc[o], off);
        #pragma unroll
        for (int h = 0; h < 4; h++) den[h] += __shfl_xor_sync(0xffffffffu, den[h], off);
    }
    if (lane == 0) {
        bool has = end > beg;
        float o0 = 0.f, o1 = 0.f;
        #pragma unroll
        for (int h = 0; h < 4; h++) {
            float r0 = has ? acc[2 * h] / den[h] : 0.f;
            float r1 = has ? acc[2 * h + 1] / den[h] : 0.f;
            r0 += r4[n * 8 + 2 * h] + b4[2 * h];
            r1 += r4[n * 8 + 2 * h + 1] + b4[2 * h + 1];
            float m = fmaxf(r0, r1);
            float e0 = expf(r0 - m), e1 = expf(r1 - m);
            float s = e0 + e1;
            o0 += e0 / s;
            o1 += e1 / s;
        }
        out[n * 2 + 0] = o0 * 0.25f;
        out[n * 2 + 1] = o1 * 0.25f;
    }
}

// ---------------- host launcher ----------------------------------------------
extern "C" void kernel_launch(void* const* d_in, const int* in_sizes, int n_in,
                              void* d_out, int out_size) {
    const float* x     = (const float*)d_in[0];
    const int*   src   = (const int*)  d_in[1];
    const int*   dst   = (const int*)  d_in[2];
    const float* W1    = (const float*)d_in[3];
    const float* al1   = (const float*)d_in[4];
    const float* ar1   = (const float*)d_in[5];
    const float* b1    = (const float*)d_in[6];
    const float* W2    = (const float*)d_in[7];
    const float* al2   = (const float*)d_in[8];
    const float* ar2   = (const float*)d_in[9];
    const float* b2    = (const float*)d_in[10];
    const float* W3    = (const float*)d_in[11];
    const float* al3   = (const float*)d_in[12];
    const float* ar3   = (const float*)d_in[13];
    const float* b3    = (const float*)d_in[14];
    const float* W4    = (const float*)d_in[15];
    const float* al4   = (const float*)d_in[16];
    const float* ar4   = (const float*)d_in[17];
    const float* b4    = (const float*)d_in[18];
    const float* resW4 = (const float*)d_in[19];
    float* out = (float*)d_out;
    const int E = in_sizes[1];

    float *feat, *hA, *hB, *el, *er, *f4, *r4;
    int *cnt, *rowptr, *cur, *csrc;
    cudaGetSymbolAddress((void**)&feat,   g_feat);
    cudaGetSymbolAddress((void**)&hA,     g_hA);
    cudaGetSymbolAddress((void**)&hB,     g_hB);
    cudaGetSymbolAddress((void**)&el,     g_el);
    cudaGetSymbolAddress((void**)&er,     g_er);
    cudaGetSymbolAddress((void**)&f4,     g_f4);
    cudaGetSymbolAddress((void**)&r4,     g_r4);
    cudaGetSymbolAddress((void**)&cnt,    g_cnt);
    cudaGetSymbolAddress((void**)&rowptr, g_rowptr);
    cudaGetSymbolAddress((void**)&cur,    g_cur);
    cudaGetSymbolAddress((void**)&csrc,   g_csrc);

    // ---- CSR by dst ----
    k_zero_cnt<<<(NN + 255) / 256, 256>>>(cnt);
    k_histo<<<1024, 256>>>(dst, cnt, E);
    k_scan_part<<<NB, 1024>>>(cnt);
    k_scan_small<<<1, 1>>>(rowptr);
    k_scan_final<<<NB, 1024>>>(cnt, rowptr, cur);
    k_scatter<<<1024, 256>>>(src, dst, cur, csrc, E);

    dim3 gemm_grid(FD / BN, (NN + BM - 1) / BM);

    // ---- layer 1: IN=128 -> (4,64), no residual, ELU ----
    k_gemm_tf32<<<gemm_grid, 256>>>(x, W1, feat, NN, FD, 128);
    k_elr<<<NN, 256>>>(feat, al1, ar1, el, er);
    k_edge_agg<<<NN, 64>>>((const float4*)feat, (const float4*)el, (const float4*)er,
                           rowptr, csrc, nullptr, (const float4*)b1, (float4*)hA);

    // ---- layer 2 ----
    k_gemm_tf32<<<gemm_grid, 256>>>(hA, W2, feat, NN, FD, FD);
    k_elr<<<NN, 256>>>(feat, al2, ar2, el, er);
    k_edge_agg<<<NN, 64>>>((const float4*)feat, (const float4*)el, (const float4*)er,
                           rowptr, csrc, (const float4*)hA, (const float4*)b2, (float4*)hB);

    // ---- layer 3 ----
    k_gemm_tf32<<<gemm_grid, 256>>>(hB, W3, feat, NN, FD, FD);
    k_elr<<<NN, 256>>>(feat, al3, ar3, el, er);
    k_edge_agg<<<NN, 64>>>((const float4*)feat, (const float4*)el, (const float4*)er,
                           rowptr, csrc, (const float4*)hB, (const float4*)b3, (float4*)hA);

    // ---- layer 4: 256 -> (4,2), fc residual, softmax, head-mean ----
    k_l4_proj<<<(NN + 7) / 8, 256>>>(hA, W4, resW4, f4, r4);
    k_elr4<<<(NN + 255) / 256, 256>>>(f4, al4, ar4, el, er);
    k_l4_edge<<<(NN + 7) / 8, 256>>>(f4, el, er, rowptr, csrc, r4, b4, out);
}

// round 4
// speedup vs baseline: 1.9412x; 1.2392x over previous
#include <cuda_runtime.h>
#include <cuda_bf16.h>
#include <cstdint>

#define NN 50000
#define EE 800000
#define FD 256          // H*HID
#define NEG 0.2f
#define NB 49           // ceil(NN/1024)

// ---------------- scratch (device globals; no allocation allowed) ------------
__device__ __nv_bfloat16 g_featb[(size_t)NN * FD];   // bf16 post-GEMM features
__device__ float g_hA[(size_t)NN * FD];
__device__ float g_hB[(size_t)NN * FD];
__device__ float g_el[NN * 4];
__device__ float g_er[NN * 4];
__device__ float g_f4[NN * 8];
__device__ float g_r4[NN * 8];
__device__ int   g_cnt[NN];
__device__ int   g_rowptr[NN + 1];
__device__ int   g_cur[NN];
__device__ int   g_csrc[EE];
__device__ int   g_bsum[64];

// ---------------- CSR build --------------------------------------------------
__global__ void k_zero_cnt(int* cnt) {
    int i = blockIdx.x * blockDim.x + threadIdx.x;
    if (i < NN) cnt[i] = 0;
}

__global__ void k_histo(const int* __restrict__ dst, int* __restrict__ cnt, int E) {
    for (int i = blockIdx.x * blockDim.x + threadIdx.x; i < E; i += gridDim.x * blockDim.x)
        atomicAdd(&cnt[dst[i]], 1);
}

__global__ void k_scan_part(const int* __restrict__ cnt) {
    __shared__ int sh[1024];
    int i = blockIdx.x * 1024 + threadIdx.x;
    sh[threadIdx.x] = (i < NN) ? cnt[i] : 0;
    __syncthreads();
    for (int o = 512; o > 0; o >>= 1) {
        if (threadIdx.x < o) sh[threadIdx.x] += sh[threadIdx.x + o];
        __syncthreads();
    }
    if (threadIdx.x == 0) g_bsum[blockIdx.x] = sh[0];
}

__global__ void k_scan_small(int* rowptr) {
    int acc = 0;
    for (int b = 0; b < NB; b++) { int v = g_bsum[b]; g_bsum[b] = acc; acc += v; }
    rowptr[NN] = acc;
}

__global__ void k_scan_final(const int* __restrict__ cnt, int* __restrict__ rowptr,
                             int* __restrict__ cur) {
    __shared__ int sh[1024];
    int tid = threadIdx.x;
    int i = blockIdx.x * 1024 + tid;
    int v = (i < NN) ? cnt[i] : 0;
    sh[tid] = v;
    __syncthreads();
    #pragma unroll
    for (int o = 1; o < 1024; o <<= 1) {
        int t = (tid >= o) ? sh[tid - o] : 0;
        __syncthreads();
        sh[tid] += t;
        __syncthreads();
    }
    if (i < NN) { int ex = g_bsum[blockIdx.x] + sh[tid] - v; rowptr[i] = ex; cur[i] = ex; }
}

__global__ void k_scatter(const int* __restrict__ src, const int* __restrict__ dst,
                          int* __restrict__ cur, int* __restrict__ csrc, int E) {
    for (int i = blockIdx.x * blockDim.x + threadIdx.x; i < E; i += gridDim.x * blockDim.x) {
        int d = dst[i];
        int p = atomicAdd(&cur[d], 1);
        csrc[p] = src[i];
    }
}

// ---------------- tf32 tensor GEMM -> bf16 out: C = A[M,K] @ B[Nc,K]^T -------
#define BM 128
#define BN 64
#define BK 32

__device__ __forceinline__ float to_tf32(float x) {
    uint32_t u;
    asm("cvt.rna.tf32.f32 %0, %1;" : "=r"(u) : "f"(x));
    return __uint_as_float(u);
}

__device__ __forceinline__ void mma_tf32(float (&d)[4], const uint32_t (&a)[4],
                                         const uint32_t (&b)[2]) {
    asm volatile(
        "mma.sync.aligned.m16n8k8.row.col.f32.tf32.tf32.f32 "
        "{%0,%1,%2,%3},{%4,%5,%6,%7},{%8,%9},{%0,%1,%2,%3};"
        : "+f"(d[0]), "+f"(d[1]), "+f"(d[2]), "+f"(d[3])
        : "r"(a[0]), "r"(a[1]), "r"(a[2]), "r"(a[3]), "r"(b[0]), "r"(b[1]));
}

__global__ void __launch_bounds__(256) k_gemm_tf32(const float* __restrict__ A,
                                                   const float* __restrict__ B,
                                                   __nv_bfloat16* __restrict__ C,
                                                   int M, int Nc, int K) {
    __shared__ float As[BK][BM + 8];
    __shared__ float Bs[BK][BN + 8];
    const int bm = blockIdx.y * BM, bn = blockIdx.x * BN;
    const int tid = threadIdx.x;
    const int warp = tid >> 5, lane = tid & 31;
    const int wm = warp & 3, wn = warp >> 2;
    const int r = lane >> 2, c = lane & 3;
    const int ar = tid >> 1, ahalf = (tid & 1) * 16;
    const int br = tid >> 2, bq = (tid & 3) * 8;

    float acc[2][4][4];
    #pragma unroll
    for (int mt = 0; mt < 2; mt++)
        #pragma unroll
        for (int nt = 0; nt < 4; nt++)
            #pragma unroll
            for (int i = 0; i < 4; i++) acc[mt][nt][i] = 0.f;

    const bool arow_ok = (bm + ar) < M;
    for (int kt = 0; kt < K; kt += BK) {
        float4 aR[4], bR[2];
        #pragma unroll
        for (int j = 0; j < 4; j++) {
            aR[j] = arow_ok ? *(const float4*)&A[(size_t)(bm + ar) * K + kt + ahalf + 4 * j]
                            : make_float4(0.f, 0.f, 0.f, 0.f);
        }
        #pragma unroll
        for (int j = 0; j < 2; j++)
            bR[j] = *(const float4*)&B[(size_t)(bn + br) * K + kt + bq + 4 * j];
        __syncthreads();
        #pragma unroll
        for (int j = 0; j < 4; j++) {
            As[ahalf + 4 * j + 0][ar] = to_tf32(aR[j].x);
            As[ahalf + 4 * j + 1][ar] = to_tf32(aR[j].y);
            As[ahalf + 4 * j + 2][ar] = to_tf32(aR[j].z);
            As[ahalf + 4 * j + 3][ar] = to_tf32(aR[j].w);
        }
        #pragma unroll
        for (int j = 0; j < 2; j++) {
            Bs[bq + 4 * j + 0][br] = to_tf32(bR[j].x);
            Bs[bq + 4 * j + 1][br] = to_tf32(bR[j].y);
            Bs[bq + 4 * j + 2][br] = to_tf32(bR[j].z);
            Bs[bq + 4 * j + 3][br] = to_tf32(bR[j].w);
        }
        __syncthreads();
        #pragma unroll
        for (int kk = 0; kk < BK; kk += 8) {
            uint32_t af[2][4], bf[4][2];
            #pragma unroll
            for (int mt = 0; mt < 2; mt++) {
                int row0 = wm * 32 + mt * 16 + r;
                af[mt][0] = __float_as_uint(As[kk + c][row0]);
                af[mt][1] = __float_as_uint(As[kk + c][row0 + 8]);
                af[mt][2] = __float_as_uint(As[kk + c + 4][row0]);
                af[mt][3] = __float_as_uint(As[kk + c + 4][row0 + 8]);
            }
            #pragma unroll
            for (int nt = 0; nt < 4; nt++) {
                int col0 = wn * 32 + nt * 8 + r;
                bf[nt][0] = __float_as_uint(Bs[kk + c][col0]);
                bf[nt][1] = __float_as_uint(Bs[kk + c + 4][col0]);
            }
            #pragma unroll
            for (int mt = 0; mt < 2; mt++)
                #pragma unroll
                for (int nt = 0; nt < 4; nt++)
                    mma_tf32(acc[mt][nt], af[mt], bf[nt]);
        }
    }
    #pragma unroll
    for (int mt = 0; mt < 2; mt++) {
        #pragma unroll
        for (int nt = 0; nt < 4; nt++) {
            int row = bm + wm * 32 + mt * 16 + r;
            int col = bn + wn * 32 + nt * 8 + 2 * c;
            if (row < M)
                *(__nv_bfloat162*)&C[(size_t)row * Nc + col] =
                    __floats2bfloat162_rn(acc[mt][nt][0], acc[mt][nt][1]);
            if (row + 8 < M)
                *(__nv_bfloat162*)&C[(size_t)(row + 8) * Nc + col] =
                    __floats2bfloat162_rn(acc[mt][nt][2], acc[mt][nt][3]);
        }
    }
}

// ---------------- el/er per node (bf16 feat) ---------------------------------
__global__ void k_elr(const __nv_bfloat16* __restrict__ feat,
                      const float* __restrict__ al, const float* __restrict__ ar,
                      float* __restrict__ el, float* __restrict__ er) {
    int n = blockIdx.x;
    int ch = threadIdx.x;                 // 256
    float f = __bfloat162float(feat[(size_t)n * FD + ch]);
    float pl = f * al[ch];
    float pr = f * ar[ch];
    #pragma unroll
    for (int o = 16; o > 0; o >>= 1) {
        pl += __shfl_down_sync(0xffffffffu, pl, o);
        pr += __shfl_down_sync(0xffffffffu, pr, o);
    }
    __shared__ float sl[8], sr[8];
    int w = ch >> 5;
    if ((ch & 31) == 0) { sl[w] = pl; sr[w] = pr; }
    __syncthreads();
    if (ch < 4) {
        el[n * 4 + ch] = sl[2 * ch] + sl[2 * ch + 1];
        er[n * 4 + ch] = sr[2 * ch] + sr[2 * ch + 1];
    }
}

// ---------------- fused edge aggregation: warp per node, bf16 gather ---------
// lane covers channels 8*lane..8*lane+7 (head = lane>>3); 4 nodes per block.
__global__ void __launch_bounds__(128) k_edge_agg(
        const uint4* __restrict__ featb,      // [N][32] x (8 bf16)
        const float4* __restrict__ el4, const float4* __restrict__ er4,
        const int* __restrict__ rowptr, const int* __restrict__ csrc,
        const float4* __restrict__ hprev4, const float4* __restrict__ bias4,
        float4* __restrict__ hout4) {
    int w = threadIdx.x >> 5;
    int n = blockIdx.x * 4 + w;
    int lane = threadIdx.x & 31;
    if (n >= NN) return;
    int head = lane >> 3;
    __shared__ int   ssrc[4][32];
    __shared__ float sw[4][32][4];
    int beg = rowptr[n], end = rowptr[n + 1];
    float4 erd = er4[n];
    float acc[8];
    #pragma unroll
    for (int i = 0; i < 8; i++) acc[i] = 0.f;
    float4 dl = make_float4(0.f, 0.f, 0.f, 0.f);
    for (int base = beg; base < end; base += 32) {
        int cnt = min(32, end - base);
        if (lane < cnt) {
            int s = csrc[base + lane];
            ssrc[w][lane] = s;
            float4 le = el4[s];
            float x0 = le.x + erd.x; x0 = x0 > 0.f ? x0 : NEG * x0;
            float x1 = le.y + erd.y; x1 = x1 > 0.f ? x1 : NEG * x1;
            float x2 = le.z + erd.z; x2 = x2 > 0.f ? x2 : NEG * x2;
            float x3 = le.w + erd.w; x3 = x3 > 0.f ? x3 : NEG * x3;
            float w0 = expf(x0), w1 = expf(x1), w2 = expf(x2), w3 = expf(x3);
            sw[w][lane][0] = w0; sw[w][lane][1] = w1;
            sw[w][lane][2] = w2; sw[w][lane][3] = w3;
            dl.x += w0; dl.y += w1; dl.z += w2; dl.w += w3;
        }
        __syncwarp();
        for (int e = 0; e < cnt; e++) {
            int s = ssrc[w][e];
            uint4 fv = featb[(size_t)s * 32 + lane];
            float wgt = sw[w][e][head];
            const __nv_bfloat162* p = (const __nv_bfloat162*)&fv;
            #pragma unroll
            for (int j = 0; j < 4; j++) {
                float2 v = __bfloat1622float2(p[j]);
                acc[2 * j]     = fmaf(v.x, wgt, acc[2 * j]);
                acc[2 * j + 1] = fmaf(v.y, wgt, acc[2 * j + 1]);
            }
        }
        __syncwarp();
    }
    // reduce per-head denominators across warp
    #pragma unroll
    for (int o = 16; o > 0; o >>= 1) {
        dl.x += __shfl_xor_sync(0xffffffffu, dl.x, o);
        dl.y += __shfl_xor_sync(0xffffffffu, dl.y, o);
        dl.z += __shfl_xor_sync(0xffffffffu, dl.z, o);
        dl.w += __shfl_xor_sync(0xffffffffu, dl.w, o);
    }
    float den = (head == 0) ? dl.x : (head == 1) ? dl.y : (head == 2) ? dl.z : dl.w;
    float inv = (end > beg) ? 1.f / den : 0.f;
    float4 b0 = bias4[lane * 2], b1 = bias4[lane * 2 + 1];
    float4 v0 = make_float4(acc[0] * inv + b0.x, acc[1] * inv + b0.y,
                            acc[2] * inv + b0.z, acc[3] * inv + b0.w);
    float4 v1 = make_float4(acc[4] * inv + b1.x, acc[5] * inv + b1.y,
                            acc[6] * inv + b1.z, acc[7] * inv + b1.w);
    if (hprev4) {
        float4 p0 = hprev4[(size_t)n * 64 + lane * 2];
        float4 p1 = hprev4[(size_t)n * 64 + lane * 2 + 1];
        v0.x += p0.x; v0.y += p0.y; v0.z += p0.z; v0.w += p0.w;
        v1.x += p1.x; v1.y += p1.y; v1.z += p1.z; v1.w += p1.w;
    }
    v0.x = v0.x > 0.f ? v0.x : expm1f(v0.x);
    v0.y = v0.y > 0.f ? v0.y : expm1f(v0.y);
    v0.z = v0.z > 0.f ? v0.z : expm1f(v0.z);
    v0.w = v0.w > 0.f ? v0.w : expm1f(v0.w);
    v1.x = v1.x > 0.f ? v1.x : expm1f(v1.x);
    v1.y = v1.y > 0.f ? v1.y : expm1f(v1.y);
    v1.z = v1.z > 0.f ? v1.z : expm1f(v1.z);
    v1.w = v1.w > 0.f ? v1.w : expm1f(v1.w);
    hout4[(size_t)n * 64 + lane * 2]     = v0;
    hout4[(size_t)n * 64 + lane * 2 + 1] = v1;
}

// ---------------- layer-4 projection ----------------------------------------
__global__ void k_l4_proj(const float* __restrict__ h, const float* __restrict__ W4,
                          const float* __restrict__ rW4, float* __restrict__ f4,
                          float* __restrict__ r4) {
    int n = blockIdx.x * 8 + (threadIdx.x >> 5);
    int lane = threadIdx.x & 31;
    if (n >= NN) return;
    float acc[16];
    #pragma unroll
    for (int o = 0; o < 16; o++) acc[o] = 0.f;
    const float* hr = h + (size_t)n * FD;
    for (int k = lane; k < FD; k += 32) {
        float hv = hr[k];
        #pragma unroll
        for (int o = 0; o < 8; o++) acc[o]     = fmaf(hv, W4[o * FD + k], acc[o]);
        #pragma unroll
        for (int o = 0; o < 8; o++) acc[8 + o] = fmaf(hv, rW4[o * FD + k], acc[8 + o]);
    }
    #pragma unroll
    for (int o = 0; o < 16; o++)
        #pragma unroll
        for (int off = 16; off > 0; off >>= 1)
            acc[o] += __shfl_xor_sync(0xffffffffu, acc[o], off);
    if (lane < 8) {
        f4[n * 8 + lane] = acc[lane];
        r4[n * 8 + lane] = acc[8 + lane];
    }
}

__global__ void k_elr4(const float* __restrict__ f4, const float* __restrict__ al4,
                       const float* __restrict__ ar4, float* __restrict__ el,
                       float* __restrict__ er) {
    int n = blockIdx.x * blockDim.x + threadIdx.x;
    if (n >= NN) return;
    float4 f0 = ((const float4*)f4)[n * 2];
    float4 f1 = ((const float4*)f4)[n * 2 + 1];
    el[n * 4 + 0] = f0.x * al4[0] + f0.y * al4[1];
    el[n * 4 + 1] = f0.z * al4[2] + f0.w * al4[3];
    el[n * 4 + 2] = f1.x * al4[4] + f1.y * al4[5];
    el[n * 4 + 3] = f1.z * al4[6] + f1.w * al4[7];
    er[n * 4 + 0] = f0.x * ar4[0] + f0.y * ar4[1];
    er[n * 4 + 1] = f0.z * ar4[2] + f0.w * ar4[3];
    er[n * 4 + 2] = f1.x * ar4[4] + f1.y * ar4[5];
    er[n * 4 + 3] = f1.z * ar4[6] + f1.w * ar4[7];
}

// ---------------- layer-4 edge agg + softmax + head-mean ---------------------
__global__ void k_l4_edge(const float* __restrict__ f4, const float* __restrict__ el,
                          const float* __restrict__ er, const int* __restrict__ rowptr,
                          const int* __restrict__ csrc, const float* __restrict__ r4,
                          const float* __restrict__ b4, float* __restrict__ out) {
    int n = blockIdx.x * 8 + (threadIdx.x >> 5);
    int lane = threadIdx.x & 31;
    if (n >= NN) return;
    int beg = rowptr[n], end = rowptr[n + 1];
    float4 erd = ((const float4*)er)[n];
    float acc[8] = {0, 0, 0, 0, 0, 0, 0, 0};
    float den[4] = {0, 0, 0, 0};
    for (int e = beg + lane; e < end; e += 32) {
        int s = csrc[e];
        float4 le = ((const float4*)el)[s];
        float x0 = le.x + erd.x; x0 = x0 > 0.f ? x0 : NEG * x0;
        float x1 = le.y + erd.y; x1 = x1 > 0.f ? x1 : NEG * x1;
        float x2 = le.z + erd.z; x2 = x2 > 0.f ? x2 : NEG * x2;
        float x3 = le.w + erd.w; x3 = x3 > 0.f ? x3 : NEG * x3;
        float w0 = expf(x0), w1 = expf(x1), w2 = expf(x2), w3 = expf(x3);
        den[0] += w0; den[1] += w1; den[2] += w2; den[3] += w3;
        float4 f0 = ((const float4*)f4)[s * 2];
        float4 f1 = ((const float4*)f4)[s * 2 + 1];
        acc[0] = fmaf(f0.x, w0, acc[0]);  acc[1] = fmaf(f0.y, w0, acc[1]);
        acc[2] = fmaf(f0.z, w1, acc[2]);  acc[3] = fmaf(f0.w, w1, acc[3]);
        acc[4] = fmaf(f1.x, w2, acc[4]);  acc[5] = fmaf(f1.y, w2, acc[5]);
        acc[6] = fmaf(f1.z, w3, acc[6]);  acc[7] = fmaf(f1.w, w3, acc[7]);
    }
    #pragma unroll
    for (int off = 16; off > 0; off >>= 1) {
        #pragma unroll
        for (int o = 0; o < 8; o++) acc[o] += __shfl_xor_sync(0xffffffffu, acc[o], off);
        #pragma unroll
        for (int h = 0; h < 4; h++) den[h] += __shfl_xor_sync(0xffffffffu, den[h], off);
    }
    if (lane == 0) {
        bool has = end > beg;
        float o0 = 0.f, o1 = 0.f;
        #pragma unroll
        for (int h = 0; h < 4; h++) {
            float r0 = has ? acc[2 * h] / den[h] : 0.f;
            float r1 = has ? acc[2 * h + 1] / den[h] : 0.f;
            r0 += r4[n * 8 + 2 * h] + b4[2 * h];
            r1 += r4[n * 8 + 2 * h + 1] + b4[2 * h + 1];
            float m = fmaxf(r0, r1);
            float e0 = expf(r0 - m), e1 = expf(r1 - m);
            float s = e0 + e1;
            o0 += e0 / s;
            o1 += e1 / s;
        }
        out[n * 2 + 0] = o0 * 0.25f;
        out[n * 2 + 1] = o1 * 0.25f;
    }
}

// ---------------- host launcher ----------------------------------------------
extern "C" void kernel_launch(void* const* d_in, const int* in_sizes, int n_in,
                              void* d_out, int out_size) {
    const float* x     = (const float*)d_in[0];
    const int*   src   = (const int*)  d_in[1];
    const int*   dst   = (const int*)  d_in[2];
    const float* W1    = (const float*)d_in[3];
    const float* al1   = (const float*)d_in[4];
    const float* ar1   = (const float*)d_in[5];
    const float* b1    = (const float*)d_in[6];
    const float* W2    = (const float*)d_in[7];
    const float* al2   = (const float*)d_in[8];
    const float* ar2   = (const float*)d_in[9];
    const float* b2    = (const float*)d_in[10];
    const float* W3    = (const float*)d_in[11];
    const float* al3   = (const float*)d_in[12];
    const float* ar3   = (const float*)d_in[13];
    const float* b3    = (const float*)d_in[14];
    const float* W4    = (const float*)d_in[15];
    const float* al4   = (const float*)d_in[16];
    const float* ar4   = (const float*)d_in[17];
    const float* b4    = (const float*)d_in[18];
    const float* resW4 = (const float*)d_in[19];
    float* out = (float*)d_out;
    const int E = in_sizes[1];

    __nv_bfloat16* featb;
    float *hA, *hB, *el, *er, *f4, *r4;
    int *cnt, *rowptr, *cur, *csrc;
    cudaGetSymbolAddress((void**)&featb,  g_featb);
    cudaGetSymbolAddress((void**)&hA,     g_hA);
    cudaGetSymbolAddress((void**)&hB,     g_hB);
    cudaGetSymbolAddress((void**)&el,     g_el);
    cudaGetSymbolAddress((void**)&er,     g_er);
    cudaGetSymbolAddress((void**)&f4,     g_f4);
    cudaGetSymbolAddress((void**)&r4,     g_r4);
    cudaGetSymbolAddress((void**)&cnt,    g_cnt);
    cudaGetSymbolAddress((void**)&rowptr, g_rowptr);
    cudaGetSymbolAddress((void**)&cur,    g_cur);
    cudaGetSymbolAddress((void**)&csrc,   g_csrc);

    // ---- CSR by dst ----
    k_zero_cnt<<<(NN + 255) / 256, 256>>>(cnt);
    k_histo<<<1024, 256>>>(dst, cnt, E);
    k_scan_part<<<NB, 1024>>>(cnt);
    k_scan_small<<<1, 1>>>(rowptr);
    k_scan_final<<<NB, 1024>>>(cnt, rowptr, cur);
    k_scatter<<<1024, 256>>>(src, dst, cur, csrc, E);

    dim3 gemm_grid(FD / BN, (NN + BM - 1) / BM);
    const int agg_grid = (NN + 3) / 4;

    // ---- layer 1 ----
    k_gemm_tf32<<<gemm_grid, 256>>>(x, W1, featb, NN, FD, 128);
    k_elr<<<NN, 256>>>(featb, al1, ar1, el, er);
    k_edge_agg<<<agg_grid, 128>>>((const uint4*)featb, (const float4*)el,
                                  (const float4*)er, rowptr, csrc, nullptr,
                                  (const float4*)b1, (float4*)hA);

    // ---- layer 2 ----
    k_gemm_tf32<<<gemm_grid, 256>>>(hA, W2, featb, NN, FD, FD);
    k_elr<<<NN, 256>>>(featb, al2, ar2, el, er);
    k_edge_agg<<<agg_grid, 128>>>((const uint4*)featb, (const float4*)el,
                                  (const float4*)er, rowptr, csrc,
                                  (const float4*)hA, (const float4*)b2, (float4*)hB);

    // ---- layer 3 ----
    k_gemm_tf32<<<gemm_grid, 256>>>(hB, W3, featb, NN, FD, FD);
    k_elr<<<NN, 256>>>(featb, al3, ar3, el, er);
    k_edge_agg<<<agg_grid, 128>>>((const uint4*)featb, (const float4*)el,
                                  (const float4*)er, rowptr, csrc,
                                  (const float4*)hB, (const float4*)b3, (float4*)hA);

    // ---- layer 4 ----
    k_l4_proj<<<(NN + 7) / 8, 256>>>(hA, W4, resW4, f4, r4);
    k_elr4<<<(NN + 255) / 256, 256>>>(f4, al4, ar4, el, er);
    k_l4_edge<<<(NN + 7) / 8, 256>>>(f4, el, er, rowptr, csrc, r4, b4, out);
}

// round 5
// speedup vs baseline: 2.4598x; 1.2672x over previous
#include <cuda_runtime.h>
#include <cuda_bf16.h>
#include <cstdint>

#define NN 50000
#define EE 800000
#define FD 256          // H*HID
#define NEG 0.2f
#define NB 49           // ceil(NN/1024)

// ---------------- scratch (device globals; no allocation allowed) ------------
__device__ __nv_bfloat16 g_featb[(size_t)NN * FD];   // bf16 post-GEMM features
__device__ float g_hA[(size_t)NN * FD];
__device__ float g_hB[(size_t)NN * FD];
__device__ float g_el[NN * 4];
__device__ float g_er[NN * 4];
__device__ float g_f4[NN * 8];
__device__ float g_r4[NN * 8];
__device__ int   g_cnt[NN];
__device__ int   g_rowptr[NN + 1];
__device__ int   g_cur[NN];
__device__ int   g_csrc[EE];
__device__ int   g_bsum[64];

// ---------------- CSR build --------------------------------------------------
__global__ void k_zero_cnt(int* cnt) {
    int i = blockIdx.x * blockDim.x + threadIdx.x;
    if (i < NN) cnt[i] = 0;
}

__global__ void k_histo(const int* __restrict__ dst, int* __restrict__ cnt, int E) {
    for (int i = blockIdx.x * blockDim.x + threadIdx.x; i < E; i += gridDim.x * blockDim.x)
        atomicAdd(&cnt[dst[i]], 1);
}

__global__ void k_scan_part(const int* __restrict__ cnt) {
    __shared__ int sh[1024];
    int i = blockIdx.x * 1024 + threadIdx.x;
    sh[threadIdx.x] = (i < NN) ? cnt[i] : 0;
    __syncthreads();
    for (int o = 512; o > 0; o >>= 1) {
        if (threadIdx.x < o) sh[threadIdx.x] += sh[threadIdx.x + o];
        __syncthreads();
    }
    if (threadIdx.x == 0) g_bsum[blockIdx.x] = sh[0];
}

__global__ void k_scan_small(int* rowptr) {
    int acc = 0;
    for (int b = 0; b < NB; b++) { int v = g_bsum[b]; g_bsum[b] = acc; acc += v; }
    rowptr[NN] = acc;
}

__global__ void k_scan_final(const int* __restrict__ cnt, int* __restrict__ rowptr,
                             int* __restrict__ cur) {
    __shared__ int sh[1024];
    int tid = threadIdx.x;
    int i = blockIdx.x * 1024 + tid;
    int v = (i < NN) ? cnt[i] : 0;
    sh[tid] = v;
    __syncthreads();
    #pragma unroll
    for (int o = 1; o < 1024; o <<= 1) {
        int t = (tid >= o) ? sh[tid - o] : 0;
        __syncthreads();
        sh[tid] += t;
        __syncthreads();
    }
    if (i < NN) { int ex = g_bsum[blockIdx.x] + sh[tid] - v; rowptr[i] = ex; cur[i] = ex; }
}

__global__ void k_scatter(const int* __restrict__ src, const int* __restrict__ dst,
                          int* __restrict__ cur, int* __restrict__ csrc, int E) {
    for (int i = blockIdx.x * blockDim.x + threadIdx.x; i < E; i += gridDim.x * blockDim.x) {
        int d = dst[i];
        int p = atomicAdd(&cur[d], 1);
        csrc[p] = src[i];
    }
}

// ---------------- tf32 GEMM (cp.async double-buffered) + fused el/er ---------
// C[M,256] = A[M,K] @ B[256,K]^T, bf16 out; blockIdx.x = head (BN=64=HID).
// Epilogue also emits el[n][head] = feat_row_head . al_head (same for er).
#define BM 128
#define BN 64
#define BK 32
#define BKP 36                    // BK + 4 pad
#define ASZ (BM * BKP)
#define BSZ (BN * BKP)
#define GEMM_SMEM ((2 * (ASZ + BSZ)) * (int)sizeof(float))

__device__ __forceinline__ void cp16(uint32_t s, const float* g) {
    asm volatile("cp.async.cg.shared.global [%0], [%1], 16;" :: "r"(s), "l"(g));
}

__device__ __forceinline__ void mma_tf32(float (&d)[4], const uint32_t (&a)[4],
                                         const uint32_t (&b)[2]) {
    asm volatile(
        "mma.sync.aligned.m16n8k8.row.col.f32.tf32.tf32.f32 "
        "{%0,%1,%2,%3},{%4,%5,%6,%7},{%8,%9},{%0,%1,%2,%3};"
        : "+f"(d[0]), "+f"(d[1]), "+f"(d[2]), "+f"(d[3])
        : "r"(a[0]), "r"(a[1]), "r"(a[2]), "r"(a[3]), "r"(b[0]), "r"(b[1]));
}

__global__ void __launch_bounds__(256) k_gemm_tf32(
        const float* __restrict__ A, const float* __restrict__ B,
        __nv_bfloat16* __restrict__ C,
        const float* __restrict__ al, const float* __restrict__ ar,
        float* __restrict__ el, float* __restrict__ er, int M, int K) {
    extern __shared__ float smem[];
    float* Asm = smem;                 // [2][BM][BKP]
    float* Bsm = smem + 2 * ASZ;       // [2][BN][BKP]
    __shared__ float sAl[BN], sAr[BN];
    __shared__ float sEl[2][BM], sEr[2][BM];

    const int head = blockIdx.x;
    const int bm = blockIdx.y * BM, bn = head * BN;
    const int tid = threadIdx.x;
    const int warp = tid >> 5, lane = tid & 31;
    const int wm = warp & 3, wn = warp >> 2;
    const int r = lane >> 2, c = lane & 3;

    if (tid < BN) { sAl[tid] = al[bn + tid]; sAr[tid] = ar[bn + tid]; }

    // loader mapping
    const int arow = tid >> 1, acol = (tid & 1) * 16;   // 16 floats (64B) per thread
    const int brow = tid >> 2, bcol = (tid & 3) * 8;    // 8 floats  (32B) per thread
    const bool aok = (bm + arow) < M;

    float acc[2][4][4];
    #pragma unroll
    for (int mt = 0; mt < 2; mt++)
        #pragma unroll
        for (int nt = 0; nt < 4; nt++)
            #pragma unroll
            for (int i = 0; i < 4; i++) acc[mt][nt][i] = 0.f;

    const int ntile = K / BK;

    // issue copy for tile kt into buffer buf
    auto issue = [&](int buf, int kt) {
        if (aok) {
            uint32_t sa = (uint32_t)__cvta_generic_to_shared(
                &Asm[(buf * BM + arow) * BKP + acol]);
            const float* ga = &A[(size_t)(bm + arow) * K + kt + acol];
            #pragma unroll
            for (int j = 0; j < 4; j++) cp16(sa + j * 16, ga + j * 4);
        }
        uint32_t sb = (uint32_t)__cvta_generic_to_shared(
            &Bsm[(buf * BN + brow) * BKP + bcol]);
        const float* gb = &B[(size_t)(bn + brow) * K + kt + bcol];
        #pragma unroll
        for (int j = 0; j < 2; j++) cp16(sb + j * 16, gb + j * 4);
    };

    issue(0, 0);
    asm volatile("cp.async.commit_group;");

    for (int t = 0; t < ntile; t++) {
        if (t + 1 < ntile) {
            issue((t + 1) & 1, (t + 1) * BK);
            asm volatile("cp.async.commit_group;");
            asm volatile("cp.async.wait_group 1;");
        } else {
            asm volatile("cp.async.wait_group 0;");
        }
        __syncthreads();
        const float* Ab = &Asm[((t & 1) * BM) * BKP];
        const float* Bb = &Bsm[((t & 1) * BN) * BKP];
        #pragma unroll
        for (int kk = 0; kk < BK; kk += 8) {
            uint32_t af[2][4], bf[4][2];
            #pragma unroll
            for (int mt = 0; mt < 2; mt++) {
                int row0 = wm * 32 + mt * 16 + r;
                af[mt][0] = __float_as_uint(Ab[row0 * BKP + kk + c]);
                af[mt][1] = __float_as_uint(Ab[(row0 + 8) * BKP + kk + c]);
                af[mt][2] = __float_as_uint(Ab[row0 * BKP + kk + c + 4]);
                af[mt][3] = __float_as_uint(Ab[(row0 + 8) * BKP + kk + c + 4]);
            }
            #pragma unroll
            for (int nt = 0; nt < 4; nt++) {
                int col0 = wn * 32 + nt * 8 + r;
                bf[nt][0] = __float_as_uint(Bb[col0 * BKP + kk + c]);
                bf[nt][1] = __float_as_uint(Bb[col0 * BKP + kk + c + 4]);
            }
            #pragma unroll
            for (int mt = 0; mt < 2; mt++)
                #pragma unroll
                for (int nt = 0; nt < 4; nt++)
                    mma_tf32(acc[mt][nt], af[mt], bf[nt]);
        }
        __syncthreads();
    }

    // ---- store bf16 feat ----
    #pragma unroll
    for (int mt = 0; mt < 2; mt++) {
        #pragma unroll
        for (int nt = 0; nt < 4; nt++) {
            int row = bm + wm * 32 + mt * 16 + r;
            int col = bn + wn * 32 + nt * 8 + 2 * c;
            if (row < M)
                *(__nv_bfloat162*)&C[(size_t)row * FD + col] =
                    __floats2bfloat162_rn(acc[mt][nt][0], acc[mt][nt][1]);
            if (row + 8 < M)
                *(__nv_bfloat162*)&C[(size_t)(row + 8) * FD + col] =
                    __floats2bfloat162_rn(acc[mt][nt][2], acc[mt][nt][3]);
        }
    }

    // ---- fused el/er: per-row dot with al/ar for this head ----
    #pragma unroll
    for (int mt = 0; mt < 2; mt++) {
        #pragma unroll
        for (int rh = 0; rh < 2; rh++) {
            float se = 0.f, sr2 = 0.f;
            #pragma unroll
            for (int nt = 0; nt < 4; nt++) {
                int col = wn * 32 + nt * 8 + 2 * c;
                float a0 = acc[mt][nt][rh * 2], a1 = acc[mt][nt][rh * 2 + 1];
                se  += a0 * sAl[col] + a1 * sAl[col + 1];
                sr2 += a0 * sAr[col] + a1 * sAr[col + 1];
            }
            se  += __shfl_xor_sync(0xffffffffu, se, 1);
            se  += __shfl_xor_sync(0xffffffffu, se, 2);
            sr2 += __shfl_xor_sync(0xffffffffu, sr2, 1);
            sr2 += __shfl_xor_sync(0xffffffffu, sr2, 2);
            if (c == 0) {
                int rowl = wm * 32 + mt * 16 + rh * 8 + r;
                sEl[wn][rowl] = se;
                sEr[wn][rowl] = sr2;
            }
        }
    }
    __syncthreads();
    if (tid < BM) {
        int row = bm + tid;
        if (row < M) {
            el[row * 4 + head] = sEl[0][tid] + sEl[1][tid];
            er[row * 4 + head] = sEr[0][tid] + sEr[1][tid];
        }
    }
}

// ---------------- fused edge aggregation: warp per node, bf16 gather ---------
__global__ void __launch_bounds__(128) k_edge_agg(
        const uint4* __restrict__ featb,      // [N][32] x (8 bf16)
        const float4* __restrict__ el4, const float4* __restrict__ er4,
        const int* __restrict__ rowptr, const int* __restrict__ csrc,
        const float4* __restrict__ hprev4, const float4* __restrict__ bias4,
        float4* __restrict__ hout4) {
    int w = threadIdx.x >> 5;
    int n = blockIdx.x * 4 + w;
    int lane = threadIdx.x & 31;
    if (n >= NN) return;
    int head = lane >> 3;
    __shared__ int   ssrc[4][32];
    __shared__ float sw[4][32][4];
    int beg = rowptr[n], end = rowptr[n + 1];
    float4 erd = er4[n];
    float acc[8];
    #pragma unroll
    for (int i = 0; i < 8; i++) acc[i] = 0.f;
    float4 dl = make_float4(0.f, 0.f, 0.f, 0.f);
    for (int base = beg; base < end; base += 32) {
        int cnt = min(32, end - base);
        if (lane < cnt) {
            int s = csrc[base + lane];
            ssrc[w][lane] = s;
            float4 le = el4[s];
            float x0 = le.x + erd.x; x0 = x0 > 0.f ? x0 : NEG * x0;
            float x1 = le.y + erd.y; x1 = x1 > 0.f ? x1 : NEG * x1;
            float x2 = le.z + erd.z; x2 = x2 > 0.f ? x2 : NEG * x2;
            float x3 = le.w + erd.w; x3 = x3 > 0.f ? x3 : NEG * x3;
            float w0 = expf(x0), w1 = expf(x1), w2 = expf(x2), w3 = expf(x3);
            sw[w][lane][0] = w0; sw[w][lane][1] = w1;
            sw[w][lane][2] = w2; sw[w][lane][3] = w3;
            dl.x += w0; dl.y += w1; dl.z += w2; dl.w += w3;
        }
        __syncwarp();
        for (int e = 0; e < cnt; e++) {
            int s = ssrc[w][e];
            uint4 fv = featb[(size_t)s * 32 + lane];
            float wgt = sw[w][e][head];
            const __nv_bfloat162* p = (const __nv_bfloat162*)&fv;
            #pragma unroll
            for (int j = 0; j < 4; j++) {
                float2 v = __bfloat1622float2(p[j]);
                acc[2 * j]     = fmaf(v.x, wgt, acc[2 * j]);
                acc[2 * j + 1] = fmaf(v.y, wgt, acc[2 * j + 1]);
            }
        }
        __syncwarp();
    }
    #pragma unroll
    for (int o = 16; o > 0; o >>= 1) {
        dl.x += __shfl_xor_sync(0xffffffffu, dl.x, o);
        dl.y += __shfl_xor_sync(0xffffffffu, dl.y, o);
        dl.z += __shfl_xor_sync(0xffffffffu, dl.z, o);
        dl.w += __shfl_xor_sync(0xffffffffu, dl.w, o);
    }
    float den = (head == 0) ? dl.x : (head == 1) ? dl.y : (head == 2) ? dl.z : dl.w;
    float inv = (end > beg) ? 1.f / den : 0.f;
    float4 b0 = bias4[lane * 2], b1 = bias4[lane * 2 + 1];
    float4 v0 = make_float4(acc[0] * inv + b0.x, acc[1] * inv + b0.y,
                            acc[2] * inv + b0.z, acc[3] * inv + b0.w);
    float4 v1 = make_float4(acc[4] * inv + b1.x, acc[5] * inv + b1.y,
                            acc[6] * inv + b1.z, acc[7] * inv + b1.w);
    if (hprev4) {
        float4 p0 = hprev4[(size_t)n * 64 + lane * 2];
        float4 p1 = hprev4[(size_t)n * 64 + lane * 2 + 1];
        v0.x += p0.x; v0.y += p0.y; v0.z += p0.z; v0.w += p0.w;
        v1.x += p1.x; v1.y += p1.y; v1.z += p1.z; v1.w += p1.w;
    }
    v0.x = v0.x > 0.f ? v0.x : expm1f(v0.x);
    v0.y = v0.y > 0.f ? v0.y : expm1f(v0.y);
    v0.z = v0.z > 0.f ? v0.z : expm1f(v0.z);
    v0.w = v0.w > 0.f ? v0.w : expm1f(v0.w);
    v1.x = v1.x > 0.f ? v1.x : expm1f(v1.x);
    v1.y = v1.y > 0.f ? v1.y : expm1f(v1.y);
    v1.z = v1.z > 0.f ? v1.z : expm1f(v1.z);
    v1.w = v1.w > 0.f ? v1.w : expm1f(v1.w);
    hout4[(size_t)n * 64 + lane * 2]     = v0;
    hout4[(size_t)n * 64 + lane * 2 + 1] = v1;
}

// ---------------- layer-4 projection ----------------------------------------
__global__ void k_l4_proj(const float* __restrict__ h, const float* __restrict__ W4,
                          const float* __restrict__ rW4, float* __restrict__ f4,
                          float* __restrict__ r4) {
    int n = blockIdx.x * 8 + (threadIdx.x >> 5);
    int lane = threadIdx.x & 31;
    if (n >= NN) return;
    float acc[16];
    #pragma unroll
    for (int o = 0; o < 16; o++) acc[o] = 0.f;
    const float* hr = h + (size_t)n * FD;
    for (int k = lane; k < FD; k += 32) {
        float hv = hr[k];
        #pragma unroll
        for (int o = 0; o < 8; o++) acc[o]     = fmaf(hv, W4[o * FD + k], acc[o]);
        #pragma unroll
        for (int o = 0; o < 8; o++) acc[8 + o] = fmaf(hv, rW4[o * FD + k], acc[8 + o]);
    }
    #pragma unroll
    for (int o = 0; o < 16; o++)
        #pragma unroll
        for (int off = 16; off > 0; off >>= 1)
            acc[o] += __shfl_xor_sync(0xffffffffu, acc[o], off);
    if (lane < 8) {
        f4[n * 8 + lane] = acc[lane];
        r4[n * 8 + lane] = acc[8 + lane];
    }
}

__global__ void k_elr4(const float* __restrict__ f4, const float* __restrict__ al4,
                       const float* __restrict__ ar4, float* __restrict__ el,
                       float* __restrict__ er) {
    int n = blockIdx.x * blockDim.x + threadIdx.x;
    if (n >= NN) return;
    float4 f0 = ((const float4*)f4)[n * 2];
    float4 f1 = ((const float4*)f4)[n * 2 + 1];
    el[n * 4 + 0] = f0.x * al4[0] + f0.y * al4[1];
    el[n * 4 + 1] = f0.z * al4[2] + f0.w * al4[3];
    el[n * 4 + 2] = f1.x * al4[4] + f1.y * al4[5];
    el[n * 4 + 3] = f1.z * al4[6] + f1.w * al4[7];
    er[n * 4 + 0] = f0.x * ar4[0] + f0.y * ar4[1];
    er[n * 4 + 1] = f0.z * ar4[2] + f0.w * ar4[3];
    er[n * 4 + 2] = f1.x * ar4[4] + f1.y * ar4[5];
    er[n * 4 + 3] = f1.z * ar4[6] + f1.w * ar4[7];
}

// ---------------- layer-4 edge agg + softmax + head-mean ---------------------
__global__ void k_l4_edge(const float* __restrict__ f4, const float* __restrict__ el,
                          const float* __restrict__ er, const int* __restrict__ rowptr,
                          const int* __restrict__ csrc, const float* __restrict__ r4,
                          const float* __restrict__ b4, float* __restrict__ out) {
    int n = blockIdx.x * 8 + (threadIdx.x >> 5);
    int lane = threadIdx.x & 31;
    if (n >= NN) return;
    int beg = rowptr[n], end = rowptr[n + 1];
    float4 erd = ((const float4*)er)[n];
    float acc[8] = {0, 0, 0, 0, 0, 0, 0, 0};
    float den[4] = {0, 0, 0, 0};
    for (int e = beg + lane; e < end; e += 32) {
        int s = csrc[e];
        float4 le = ((const float4*)el)[s];
        float x0 = le.x + erd.x; x0 = x0 > 0.f ? x0 : NEG * x0;
        float x1 = le.y + erd.y; x1 = x1 > 0.f ? x1 : NEG * x1;
        float x2 = le.z + erd.z; x2 = x2 > 0.f ? x2 : NEG * x2;
        float x3 = le.w + erd.w; x3 = x3 > 0.f ? x3 : NEG * x3;
        float w0 = expf(x0), w1 = expf(x1), w2 = expf(x2), w3 = expf(x3);
        den[0] += w0; den[1] += w1; den[2] += w2; den[3] += w3;
        float4 f0 = ((const float4*)f4)[s * 2];
        float4 f1 = ((const float4*)f4)[s * 2 + 1];
        acc[0] = fmaf(f0.x, w0, acc[0]);  acc[1] = fmaf(f0.y, w0, acc[1]);
        acc[2] = fmaf(f0.z, w1, acc[2]);  acc[3] = fmaf(f0.w, w1, acc[3]);
        acc[4] = fmaf(f1.x, w2, acc[4]);  acc[5] = fmaf(f1.y, w2, acc[5]);
        acc[6] = fmaf(f1.z, w3, acc[6]);  acc[7] = fmaf(f1.w, w3, acc[7]);
    }
    #pragma unroll
    for (int off = 16; off > 0; off >>= 1) {
        #pragma unroll
        for (int o = 0; o < 8; o++) acc[o] += __shfl_xor_sync(0xffffffffu, acc[o], off);
        #pragma unroll
        for (int h = 0; h < 4; h++) den[h] += __shfl_xor_sync(0xffffffffu, den[h], off);
    }
    if (lane == 0) {
        bool has = end > beg;
        float o0 = 0.f, o1 = 0.f;
        #pragma unroll
        for (int h = 0; h < 4; h++) {
            float r0 = has ? acc[2 * h] / den[h] : 0.f;
            float r1 = has ? acc[2 * h + 1] / den[h] : 0.f;
            r0 += r4[n * 8 + 2 * h] + b4[2 * h];
            r1 += r4[n * 8 + 2 * h + 1] + b4[2 * h + 1];
            float m = fmaxf(r0, r1);
            float e0 = expf(r0 - m), e1 = expf(r1 - m);
            float s = e0 + e1;
            o0 += e0 / s;
            o1 += e1 / s;
        }
        out[n * 2 + 0] = o0 * 0.25f;
        out[n * 2 + 1] = o1 * 0.25f;
    }
}

// ---------------- host launcher ----------------------------------------------
extern "C" void kernel_launch(void* const* d_in, const int* in_sizes, int n_in,
                              void* d_out, int out_size) {
    const float* x     = (const float*)d_in[0];
    const int*   src   = (const int*)  d_in[1];
    const int*   dst   = (const int*)  d_in[2];
    const float* W1    = (const float*)d_in[3];
    const float* al1   = (const float*)d_in[4];
    const float* ar1   = (const float*)d_in[5];
    const float* b1    = (const float*)d_in[6];
    const float* W2    = (const float*)d_in[7];
    const float* al2   = (const float*)d_in[8];
    const float* ar2   = (const float*)d_in[9];
    const float* b2    = (const float*)d_in[10];
    const float* W3    = (const float*)d_in[11];
    const float* al3   = (const float*)d_in[12];
    const float* ar3   = (const float*)d_in[13];
    const float* b3    = (const float*)d_in[14];
    const float* W4    = (const float*)d_in[15];
    const float* al4   = (const float*)d_in[16];
    const float* ar4   = (const float*)d_in[17];
    const float* b4    = (const float*)d_in[18];
    const float* resW4 = (const float*)d_in[19];
    float* out = (float*)d_out;
    const int E = in_sizes[1];

    __nv_bfloat16* featb;
    float *hA, *hB, *el, *er, *f4, *r4;
    int *cnt, *rowptr, *cur, *csrc;
    cudaGetSymbolAddress((void**)&featb,  g_featb);
    cudaGetSymbolAddress((void**)&hA,     g_hA);
    cudaGetSymbolAddress((void**)&hB,     g_hB);
    cudaGetSymbolAddress((void**)&el,     g_el);
    cudaGetSymbolAddress((void**)&er,     g_er);
    cudaGetSymbolAddress((void**)&f4,     g_f4);
    cudaGetSymbolAddress((void**)&r4,     g_r4);
    cudaGetSymbolAddress((void**)&cnt,    g_cnt);
    cudaGetSymbolAddress((void**)&rowptr, g_rowptr);
    cudaGetSymbolAddress((void**)&cur,    g_cur);
    cudaGetSymbolAddress((void**)&csrc,   g_csrc);

    cudaFuncSetAttribute(k_gemm_tf32,
                         cudaFuncAttributeMaxDynamicSharedMemorySize, GEMM_SMEM);

    // ---- CSR by dst ----
    k_zero_cnt<<<(NN + 255) / 256, 256>>>(cnt);
    k_histo<<<1024, 256>>>(dst, cnt, E);
    k_scan_part<<<NB, 1024>>>(cnt);
    k_scan_small<<<1, 1>>>(rowptr);
    k_scan_final<<<NB, 1024>>>(cnt, rowptr, cur);
    k_scatter<<<1024, 256>>>(src, dst, cur, csrc, E);

    dim3 gemm_grid(FD / BN, (NN + BM - 1) / BM);
    const int agg_grid = (NN + 3) / 4;

    // ---- layer 1 ----
    k_gemm_tf32<<<gemm_grid, 256, GEMM_SMEM>>>(x, W1, featb, al1, ar1, el, er, NN, 128);
    k_edge_agg<<<agg_grid, 128>>>((const uint4*)featb, (const float4*)el,
                                  (const float4*)er, rowptr, csrc, nullptr,
                                  (const float4*)b1, (float4*)hA);

    // ---- layer 2 ----
    k_gemm_tf32<<<gemm_grid, 256, GEMM_SMEM>>>(hA, W2, featb, al2, ar2, el, er, NN, FD);
    k_edge_agg<<<agg_grid, 128>>>((const uint4*)featb, (const float4*)el,
                                  (const float4*)er, rowptr, csrc,
                                  (const float4*)hA, (const float4*)b2, (float4*)hB);

    // ---- layer 3 ----
    k_gemm_tf32<<<gemm_grid, 256, GEMM_SMEM>>>(hB, W3, featb, al3, ar3, el, er, NN, FD);
    k_edge_agg<<<agg_grid, 128>>>((const uint4*)featb, (const float4*)el,
                                  (const float4*)er, rowptr, csrc,
                                  (const float4*)hB, (const float4*)b3, (float4*)hA);

    // ---- layer 4 ----
    k_l4_proj<<<(NN + 7) / 8, 256>>>(hA, W4, resW4, f4, r4);
    k_elr4<<<(NN + 255) / 256, 256>>>(f4, al4, ar4, el, er);
    k_l4_edge<<<(NN + 7) / 8, 256>>>(f4, el, er, rowptr, csrc, r4, b4, out);
}

// round 7
// speedup vs baseline: 2.8719x; 1.1675x over previous
#include <cuda_runtime.h>
#include <cuda_bf16.h>
#include <cstdint>
#include <cstring>

#define NN 50000
#define EE 800000
#define FD 256          // H*HID
#define NEG 0.2f
#define NB 49           // ceil(NN/1024)

__device__ __forceinline__ uint32_t bf2_as_u32(__nv_bfloat162 v) {
    uint32_t u;
    memcpy(&u, &v, 4);
    return u;
}

// ---------------- scratch (device globals; no allocation allowed) ------------
__device__ __nv_bfloat16 g_featb[(size_t)NN * FD];   // bf16 post-GEMM features
__device__ __nv_bfloat16 g_xb[(size_t)NN * 128];     // bf16 input x
__device__ __nv_bfloat16 g_hinb[(size_t)NN * FD];    // bf16 GEMM input (layers 2,3)
__device__ __nv_bfloat16 g_W1b[256 * 128];
__device__ __nv_bfloat16 g_W2b[256 * 256];
__device__ __nv_bfloat16 g_W3b[256 * 256];
__device__ float g_hA[(size_t)NN * FD];
__device__ float g_hB[(size_t)NN * FD];
__device__ float g_el[NN * 4];
__device__ float g_er[NN * 4];
__device__ float g_f4[NN * 8];
__device__ float g_r4[NN * 8];
__device__ int   g_cnt[NN];
__device__ int   g_rowptr[NN + 1];
__device__ int   g_cur[NN];
__device__ int   g_csrc[EE];
__device__ int   g_bsum[64];

// ---------------- fp32 -> bf16 converts --------------------------------------
__global__ void k_cvt(const float4* __restrict__ in, uint2* __restrict__ out, int n4) {
    int i = blockIdx.x * blockDim.x + threadIdx.x;
    if (i >= n4) return;
    float4 v = in[i];
    uint2 o;
    o.x = bf2_as_u32(__floats2bfloat162_rn(v.x, v.y));
    o.y = bf2_as_u32(__floats2bfloat162_rn(v.z, v.w));
    out[i] = o;
}

__global__ void k_cvtW(const float4* __restrict__ w1, uint2* __restrict__ o1,
                       const float4* __restrict__ w2, uint2* __restrict__ o2,
                       const float4* __restrict__ w3, uint2* __restrict__ o3) {
    int i = blockIdx.x * blockDim.x + threadIdx.x;
    // w1: 256*128/4 = 8192; w2,w3: 256*256/4 = 16384 each
    if (i < 8192) {
        float4 v = w1[i];
        o1[i] = make_uint2(bf2_as_u32(__floats2bfloat162_rn(v.x, v.y)),
                           bf2_as_u32(__floats2bfloat162_rn(v.z, v.w)));
    }
    if (i < 16384) {
        float4 v = w2[i];
        o2[i] = make_uint2(bf2_as_u32(__floats2bfloat162_rn(v.x, v.y)),
                           bf2_as_u32(__floats2bfloat162_rn(v.z, v.w)));
        float4 u = w3[i];
        o3[i] = make_uint2(bf2_as_u32(__floats2bfloat162_rn(u.x, u.y)),
                           bf2_as_u32(__floats2bfloat162_rn(u.z, u.w)));
    }
}

// ---------------- CSR build --------------------------------------------------
__global__ void k_zero_cnt(int* cnt) {
    int i = blockIdx.x * blockDim.x + threadIdx.x;
    if (i < NN) cnt[i] = 0;
}

__global__ void k_histo(const int* __restrict__ dst, int* __restrict__ cnt, int E) {
    for (int i = blockIdx.x * blockDim.x + threadIdx.x; i < E; i += gridDim.x * blockDim.x)
        atomicAdd(&cnt[dst[i]], 1);
}

__global__ void k_scan_part(const int* __restrict__ cnt) {
    __shared__ int sh[1024];
    int i = blockIdx.x * 1024 + threadIdx.x;
    sh[threadIdx.x] = (i < NN) ? cnt[i] : 0;
    __syncthreads();
    for (int o = 512; o > 0; o >>= 1) {
        if (threadIdx.x < o) sh[threadIdx.x] += sh[threadIdx.x + o];
        __syncthreads();
    }
    if (threadIdx.x == 0) g_bsum[blockIdx.x] = sh[0];
}

__global__ void k_scan_small(int* rowptr) {
    int acc = 0;
    for (int b = 0; b < NB; b++) { int v = g_bsum[b]; g_bsum[b] = acc; acc += v; }
    rowptr[NN] = acc;
}

__global__ void k_scan_final(const int* __restrict__ cnt, int* __restrict__ rowptr,
                             int* __restrict__ cur) {
    __shared__ int sh[1024];
    int tid = threadIdx.x;
    int i = blockIdx.x * 1024 + tid;
    int v = (i < NN) ? cnt[i] : 0;
    sh[tid] = v;
    __syncthreads();
    #pragma unroll
    for (int o = 1; o < 1024; o <<= 1) {
        int t = (tid >= o) ? sh[tid - o] : 0;
        __syncthreads();
        sh[tid] += t;
        __syncthreads();
    }
    if (i < NN) { int ex = g_bsum[blockIdx.x] + sh[tid] - v; rowptr[i] = ex; cur[i] = ex; }
}

__global__ void k_scatter(const int* __restrict__ src, const int* __restrict__ dst,
                          int* __restrict__ cur, int* __restrict__ csrc, int E) {
    for (int i = blockIdx.x * blockDim.x + threadIdx.x; i < E; i += gridDim.x * blockDim.x) {
        int d = dst[i];
        int p = atomicAdd(&cur[d], 1);
        csrc[p] = src[i];
    }
}

// ---------------- bf16 GEMM (cp.async double-buffered) + fused el/er ---------
// C[M,256] = A[M,K] @ B[256,K]^T, bf16 in/out, fp32 accum.
// blockIdx.x = head (BN=64=HID). Epilogue emits el/er[n][head] in fp32.
#define BM 128
#define BN 64
#define BKB 64                    // bf16 k per stage
#define BKBP 72                   // +8 pad
#define ASZB (BM * BKBP)
#define BSZB (BN * BKBP)
#define GEMM_SMEM ((2 * (ASZB + BSZB)) * (int)sizeof(__nv_bfloat16))

__device__ __forceinline__ void cp16(uint32_t s, const void* g) {
    asm volatile("cp.async.cg.shared.global [%0], [%1], 16;" :: "r"(s), "l"(g));
}

__device__ __forceinline__ void mma_bf16(float (&d)[4], const uint32_t (&a)[4],
                                         const uint32_t (&b)[2]) {
    asm volatile(
        "mma.sync.aligned.m16n8k16.row.col.f32.bf16.bf16.f32 "
        "{%0,%1,%2,%3},{%4,%5,%6,%7},{%8,%9},{%0,%1,%2,%3};"
        : "+f"(d[0]), "+f"(d[1]), "+f"(d[2]), "+f"(d[3])
        : "r"(a[0]), "r"(a[1]), "r"(a[2]), "r"(a[3]), "r"(b[0]), "r"(b[1]));
}

__global__ void __launch_bounds__(256) k_gemm_bf16(
        const __nv_bfloat16* __restrict__ A, const __nv_bfloat16* __restrict__ B,
        __nv_bfloat16* __restrict__ C,
        const float* __restrict__ al, const float* __restrict__ ar,
        float* __restrict__ el, float* __restrict__ er, int M, int K) {
    extern __shared__ __nv_bfloat16 smem[];
    __nv_bfloat16* Asm = smem;                 // [2][BM][BKBP]
    __nv_bfloat16* Bsm = smem + 2 * ASZB;      // [2][BN][BKBP]
    __shared__ float sAl[BN], sAr[BN];
    __shared__ float sEl[2][BM], sEr[2][BM];

    const int head = blockIdx.x;
    const int bm = blockIdx.y * BM, bn = head * BN;
    const int tid = threadIdx.x;
    const int warp = tid >> 5, lane = tid & 31;
    const int wm = warp & 3, wn = warp >> 2;
    const int r = lane >> 2, c = lane & 3;

    if (tid < BN) { sAl[tid] = al[bn + tid]; sAr[tid] = ar[bn + tid]; }

    const int arow = tid >> 1, acol = (tid & 1) * 32;
    const int brow = tid >> 2, bcol = (tid & 3) * 16;
    const bool aok = (bm + arow) < M;

    float acc[2][4][4];
    #pragma unroll
    for (int mt = 0; mt < 2; mt++)
        #pragma unroll
        for (int nt = 0; nt < 4; nt++)
            #pragma unroll
            for (int i = 0; i < 4; i++) acc[mt][nt][i] = 0.f;

    const int ntile = K / BKB;

    auto issue = [&](int buf, int kt) {
        if (aok) {
            uint32_t sa = (uint32_t)__cvta_generic_to_shared(
                &Asm[(buf * BM + arow) * BKBP + acol]);
            const __nv_bfloat16* ga = &A[(size_t)(bm + arow) * K + kt + acol];
            #pragma unroll
            for (int j = 0; j < 4; j++) cp16(sa + j * 16, ga + j * 8);
        }
        uint32_t sb = (uint32_t)__cvta_generic_to_shared(
            &Bsm[(buf * BN + brow) * BKBP + bcol]);
        const __nv_bfloat16* gb = &B[(size_t)(bn + brow) * K + kt + bcol];
        #pragma unroll
        for (int j = 0; j < 2; j++) cp16(sb + j * 16, gb + j * 8);
    };

    issue(0, 0);
    asm volatile("cp.async.commit_group;");

    for (int t = 0; t < ntile; t++) {
        if (t + 1 < ntile) {
            issue((t + 1) & 1, (t + 1) * BKB);
            asm volatile("cp.async.commit_group;");
            asm volatile("cp.async.wait_group 1;");
        } else {
            asm volatile("cp.async.wait_group 0;");
        }
        __syncthreads();
        const __nv_bfloat16* Ab = &Asm[((t & 1) * BM) * BKBP];
        const __nv_bfloat16* Bb = &Bsm[((t & 1) * BN) * BKBP];
        #pragma unroll
        for (int kk = 0; kk < BKB; kk += 16) {
            uint32_t af[2][4], bf[4][2];
            #pragma unroll
            for (int mt = 0; mt < 2; mt++) {
                int row0 = wm * 32 + mt * 16 + r;
                af[mt][0] = *(const uint32_t*)&Ab[row0 * BKBP + kk + 2 * c];
                af[mt][1] = *(const uint32_t*)&Ab[(row0 + 8) * BKBP + kk + 2 * c];
                af[mt][2] = *(const uint32_t*)&Ab[row0 * BKBP + kk + 2 * c + 8];
                af[mt][3] = *(const uint32_t*)&Ab[(row0 + 8) * BKBP + kk + 2 * c + 8];
            }
            #pragma unroll
            for (int nt = 0; nt < 4; nt++) {
                int col0 = wn * 32 + nt * 8 + r;
                bf[nt][0] = *(const uint32_t*)&Bb[col0 * BKBP + kk + 2 * c];
                bf[nt][1] = *(const uint32_t*)&Bb[col0 * BKBP + kk + 2 * c + 8];
            }
            #pragma unroll
            for (int mt = 0; mt < 2; mt++)
                #pragma unroll
                for (int nt = 0; nt < 4; nt++)
                    mma_bf16(acc[mt][nt], af[mt], bf[nt]);
        }
        __syncthreads();
    }

    // ---- store bf16 feat ----
    #pragma unroll
    for (int mt = 0; mt < 2; mt++) {
        #pragma unroll
        for (int nt = 0; nt < 4; nt++) {
            int row = bm + wm * 32 + mt * 16 + r;
            int col = bn + wn * 32 + nt * 8 + 2 * c;
            if (row < M)
                *(__nv_bfloat162*)&C[(size_t)row * FD + col] =
                    __floats2bfloat162_rn(acc[mt][nt][0], acc[mt][nt][1]);
            if (row + 8 < M)
                *(__nv_bfloat162*)&C[(size_t)(row + 8) * FD + col] =
                    __floats2bfloat162_rn(acc[mt][nt][2], acc[mt][nt][3]);
        }
    }

    // ---- fused el/er: per-row dot with al/ar for this head (fp32 accs) ----
    #pragma unroll
    for (int mt = 0; mt < 2; mt++) {
        #pragma unroll
        for (int rh = 0; rh < 2; rh++) {
            float se = 0.f, sr2 = 0.f;
            #pragma unroll
            for (int nt = 0; nt < 4; nt++) {
                int col = wn * 32 + nt * 8 + 2 * c;
                float a0 = acc[mt][nt][rh * 2], a1 = acc[mt][nt][rh * 2 + 1];
                se  += a0 * sAl[col] + a1 * sAl[col + 1];
                sr2 += a0 * sAr[col] + a1 * sAr[col + 1];
            }
            se  += __shfl_xor_sync(0xffffffffu, se, 1);
            se  += __shfl_xor_sync(0xffffffffu, se, 2);
            sr2 += __shfl_xor_sync(0xffffffffu, sr2, 1);
            sr2 += __shfl_xor_sync(0xffffffffu, sr2, 2);
            if (c == 0) {
                int rowl = wm * 32 + mt * 16 + rh * 8 + r;
                sEl[wn][rowl] = se;
                sEr[wn][rowl] = sr2;
            }
        }
    }
    __syncthreads();
    if (tid < BM) {
        int row = bm + tid;
        if (row < M) {
            el[row * 4 + head] = sEl[0][tid] + sEl[1][tid];
            er[row * 4 + head] = sEr[0][tid] + sEr[1][tid];
        }
    }
}

// ---------------- fused edge aggregation: warp per node, bf16 gather ---------
// Writes fp32 h (residual path) and optional bf16 shadow (next GEMM input).
__global__ void __launch_bounds__(128) k_edge_agg(
        const uint4* __restrict__ featb,      // [N][32] x (8 bf16)
        const float4* __restrict__ el4, const float4* __restrict__ er4,
        const int* __restrict__ rowptr, const int* __restrict__ csrc,
        const float4* __restrict__ hprev4, const float4* __restrict__ bias4,
        float4* __restrict__ hout4, uint4* __restrict__ houtb) {
    int w = threadIdx.x >> 5;
    int n = blockIdx.x * 4 + w;
    int lane = threadIdx.x & 31;
    if (n >= NN) return;
    int head = lane >> 3;
    __shared__ int   ssrc[4][32];
    __shared__ float sw[4][32][4];
    int beg = rowptr[n], end = rowptr[n + 1];
    float4 erd = er4[n];
    float acc[8];
    #pragma unroll
    for (int i = 0; i < 8; i++) acc[i] = 0.f;
    float4 dl = make_float4(0.f, 0.f, 0.f, 0.f);
    for (int base = beg; base < end; base += 32) {
        int cnt = min(32, end - base);
        if (lane < cnt) {
            int s = csrc[base + lane];
            ssrc[w][lane] = s;
            float4 le = el4[s];
            float x0 = le.x + erd.x; x0 = x0 > 0.f ? x0 : NEG * x0;
            float x1 = le.y + erd.y; x1 = x1 > 0.f ? x1 : NEG * x1;
            float x2 = le.z + erd.z; x2 = x2 > 0.f ? x2 : NEG * x2;
            float x3 = le.w + erd.w; x3 = x3 > 0.f ? x3 : NEG * x3;
            float w0 = expf(x0), w1 = expf(x1), w2 = expf(x2), w3 = expf(x3);
            sw[w][lane][0] = w0; sw[w][lane][1] = w1;
            sw[w][lane][2] = w2; sw[w][lane][3] = w3;
            dl.x += w0; dl.y += w1; dl.z += w2; dl.w += w3;
        }
        __syncwarp();
        for (int e = 0; e < cnt; e++) {
            int s = ssrc[w][e];
            uint4 fv = featb[(size_t)s * 32 + lane];
            float wgt = sw[w][e][head];
            const __nv_bfloat162* p = (const __nv_bfloat162*)&fv;
            #pragma unroll
            for (int j = 0; j < 4; j++) {
                float2 v = __bfloat1622float2(p[j]);
                acc[2 * j]     = fmaf(v.x, wgt, acc[2 * j]);
                acc[2 * j + 1] = fmaf(v.y, wgt, acc[2 * j + 1]);
            }
        }
        __syncwarp();
    }
    #pragma unroll
    for (int o = 16; o > 0; o >>= 1) {
        dl.x += __shfl_xor_sync(0xffffffffu, dl.x, o);
        dl.y += __shfl_xor_sync(0xffffffffu, dl.y, o);
        dl.z += __shfl_xor_sync(0xffffffffu, dl.z, o);
        dl.w += __shfl_xor_sync(0xffffffffu, dl.w, o);
    }
    float den = (head == 0) ? dl.x : (head == 1) ? dl.y : (head == 2) ? dl.z : dl.w;
    float inv = (end > beg) ? 1.f / den : 0.f;
    float4 b0 = bias4[lane * 2], b1 = bias4[lane * 2 + 1];
    float4 v0 = make_float4(acc[0] * inv + b0.x, acc[1] * inv + b0.y,
                            acc[2] * inv + b0.z, acc[3] * inv + b0.w);
    float4 v1 = make_float4(acc[4] * inv + b1.x, acc[5] * inv + b1.y,
                            acc[6] * inv + b1.z, acc[7] * inv + b1.w);
    if (hprev4) {
        float4 p0 = hprev4[(size_t)n * 64 + lane * 2];
        float4 p1 = hprev4[(size_t)n * 64 + lane * 2 + 1];
        v0.x += p0.x; v0.y += p0.y; v0.z += p0.z; v0.w += p0.w;
        v1.x += p1.x; v1.y += p1.y; v1.z += p1.z; v1.w += p1.w;
    }
    v0.x = v0.x > 0.f ? v0.x : expm1f(v0.x);
    v0.y = v0.y > 0.f ? v0.y : expm1f(v0.y);
    v0.z = v0.z > 0.f ? v0.z : expm1f(v0.z);
    v0.w = v0.w > 0.f ? v0.w : expm1f(v0.w);
    v1.x = v1.x > 0.f ? v1.x : expm1f(v1.x);
    v1.y = v1.y > 0.f ? v1.y : expm1f(v1.y);
    v1.z = v1.z > 0.f ? v1.z : expm1f(v1.z);
    v1.w = v1.w > 0.f ? v1.w : expm1f(v1.w);
    hout4[(size_t)n * 64 + lane * 2]     = v0;
    hout4[(size_t)n * 64 + lane * 2 + 1] = v1;
    if (houtb) {
        uint4 ob;
        ob.x = bf2_as_u32(__floats2bfloat162_rn(v0.x, v0.y));
        ob.y = bf2_as_u32(__floats2bfloat162_rn(v0.z, v0.w));
        ob.z = bf2_as_u32(__floats2bfloat162_rn(v1.x, v1.y));
        ob.w = bf2_as_u32(__floats2bfloat162_rn(v1.z, v1.w));
        houtb[(size_t)n * 32 + lane] = ob;
    }
}

// ---------------- layer-4 projection + el/er (merged) ------------------------
__global__ void k_l4_proj(const float* __restrict__ h, const float* __restrict__ W4,
                          const float* __restrict__ rW4,
                          const float* __restrict__ al4, const float* __restrict__ ar4,
                          float* __restrict__ f4, float* __restrict__ r4,
                          float* __restrict__ el, float* __restrict__ er) {
    int n = blockIdx.x * 8 + (threadIdx.x >> 5);
    int lane = threadIdx.x & 31;
    if (n >= NN) return;
    float acc[16];
    #pragma unroll
    for (int o = 0; o < 16; o++) acc[o] = 0.f;
    const float* hr = h + (size_t)n * FD;
    for (int k = lane; k < FD; k += 32) {
        float hv = hr[k];
        #pragma unroll
        for (int o = 0; o < 8; o++) acc[o]     = fmaf(hv, W4[o * FD + k], acc[o]);
        #pragma unroll
        for (int o = 0; o < 8; o++) acc[8 + o] = fmaf(hv, rW4[o * FD + k], acc[8 + o]);
    }
    #pragma unroll
    for (int o = 0; o < 16; o++)
        #pragma unroll
        for (int off = 16; off > 0; off >>= 1)
            acc[o] += __shfl_xor_sync(0xffffffffu, acc[o], off);
    if (lane < 8) {
        f4[n * 8 + lane] = acc[lane];
        r4[n * 8 + lane] = acc[8 + lane];
    }
    if (lane < 4) {
        el[n * 4 + lane] = acc[2 * lane] * al4[2 * lane] +
                           acc[2 * lane + 1] * al4[2 * lane + 1];
        er[n * 4 + lane] = acc[2 * lane] * ar4[2 * lane] +
                           acc[2 * lane + 1] * ar4[2 * lane + 1];
    }
}

// ---------------- layer-4 edge agg + softmax + head-mean ---------------------
__global__ void k_l4_edge(const float* __restrict__ f4, const float* __restrict__ el,
                          const float* __restrict__ er, const int* __restrict__ rowptr,
                          const int* __restrict__ csrc, const float* __restrict__ r4,
                          const float* __restrict__ b4, float* __restrict__ out) {
    int n = blockIdx.x * 8 + (threadIdx.x >> 5);
    int lane = threadIdx.x & 31;
    if (n >= NN) return;
    int beg = rowptr[n], end = rowptr[n + 1];
    float4 erd = ((const float4*)er)[n];
    float acc[8] = {0, 0, 0, 0, 0, 0, 0, 0};
    float den[4] = {0, 0, 0, 0};
    for (int e = beg + lane; e < end; e += 32) {
        int s = csrc[e];
        float4 le = ((const float4*)el)[s];
        float x0 = le.x + erd.x; x0 = x0 > 0.f ? x0 : NEG * x0;
        float x1 = le.y + erd.y; x1 = x1 > 0.f ? x1 : NEG * x1;
        float x2 = le.z + erd.z; x2 = x2 > 0.f ? x2 : NEG * x2;
        float x3 = le.w + erd.w; x3 = x3 > 0.f ? x3 : NEG * x3;
        float w0 = expf(x0), w1 = expf(x1), w2 = expf(x2), w3 = expf(x3);
        den[0] += w0; den[1] += w1; den[2] += w2; den[3] += w3;
        float4 f0 = ((const float4*)f4)[s * 2];
        float4 f1 = ((const float4*)f4)[s * 2 + 1];
        acc[0] = fmaf(f0.x, w0, acc[0]);  acc[1] = fmaf(f0.y, w0, acc[1]);
        acc[2] = fmaf(f0.z, w1, acc[2]);  acc[3] = fmaf(f0.w, w1, acc[3]);
        acc[4] = fmaf(f1.x, w2, acc[4]);  acc[5] = fmaf(f1.y, w2, acc[5]);
        acc[6] = fmaf(f1.z, w3, acc[6]);  acc[7] = fmaf(f1.w, w3, acc[7]);
    }
    #pragma unroll
    for (int off = 16; off > 0; off >>= 1) {
        #pragma unroll
        for (int o = 0; o < 8; o++) acc[o] += __shfl_xor_sync(0xffffffffu, acc[o], off);
        #pragma unroll
        for (int h = 0; h < 4; h++) den[h] += __shfl_xor_sync(0xffffffffu, den[h], off);
    }
    if (lane == 0) {
        bool has = end > beg;
        float o0 = 0.f, o1 = 0.f;
        #pragma unroll
        for (int h = 0; h < 4; h++) {
            float r0 = has ? acc[2 * h] / den[h] : 0.f;
            float r1 = has ? acc[2 * h + 1] / den[h] : 0.f;
            r0 += r4[n * 8 + 2 * h] + b4[2 * h];
            r1 += r4[n * 8 + 2 * h + 1] + b4[2 * h + 1];
            float m = fmaxf(r0, r1);
            float e0 = expf(r0 - m), e1 = expf(r1 - m);
            float s = e0 + e1;
            o0 += e0 / s;
            o1 += e1 / s;
        }
        out[n * 2 + 0] = o0 * 0.25f;
        out[n * 2 + 1] = o1 * 0.25f;
    }
}

// ---------------- host launcher ----------------------------------------------
extern "C" void kernel_launch(void* const* d_in, const int* in_sizes, int n_in,
                              void* d_out, int out_size) {
    const float* x     = (const float*)d_in[0];
    const int*   src   = (const int*)  d_in[1];
    const int*   dst   = (const int*)  d_in[2];
    const float* W1    = (const float*)d_in[3];
    const float* al1   = (const float*)d_in[4];
    const float* ar1   = (const float*)d_in[5];
    const float* b1    = (const float*)d_in[6];
    const float* W2    = (const float*)d_in[7];
    const float* al2   = (const float*)d_in[8];
    const float* ar2   = (const float*)d_in[9];
    const float* b2    = (const float*)d_in[10];
    const float* W3    = (const float*)d_in[11];
    const float* al3   = (const float*)d_in[12];
    const float* ar3   = (const float*)d_in[13];
    const float* b3    = (const float*)d_in[14];
    const float* W4    = (const float*)d_in[15];
    const float* al4   = (const float*)d_in[16];
    const float* ar4   = (const float*)d_in[17];
    const float* b4    = (const float*)d_in[18];
    const float* resW4 = (const float*)d_in[19];
    float* out = (float*)d_out;
    const int E = in_sizes[1];

    __nv_bfloat16 *featb, *xb, *hinb, *W1b, *W2b, *W3b;
    float *hA, *hB, *el, *er, *f4, *r4;
    int *cnt, *rowptr, *cur, *csrc;
    cudaGetSymbolAddress((void**)&featb,  g_featb);
    cudaGetSymbolAddress((void**)&xb,     g_xb);
    cudaGetSymbolAddress((void**)&hinb,   g_hinb);
    cudaGetSymbolAddress((void**)&W1b,    g_W1b);
    cudaGetSymbolAddress((void**)&W2b,    g_W2b);
    cudaGetSymbolAddress((void**)&W3b,    g_W3b);
    cudaGetSymbolAddress((void**)&hA,     g_hA);
    cudaGetSymbolAddress((void**)&hB,     g_hB);
    cudaGetSymbolAddress((void**)&el,     g_el);
    cudaGetSymbolAddress((void**)&er,     g_er);
    cudaGetSymbolAddress((void**)&f4,     g_f4);
    cudaGetSymbolAddress((void**)&r4,     g_r4);
    cudaGetSymbolAddress((void**)&cnt,    g_cnt);
    cudaGetSymbolAddress((void**)&rowptr, g_rowptr);
    cudaGetSymbolAddress((void**)&cur,    g_cur);
    cudaGetSymbolAddress((void**)&csrc,   g_csrc);

    cudaFuncSetAttribute(k_gemm_bf16,
                         cudaFuncAttributeMaxDynamicSharedMemorySize, GEMM_SMEM);

    // ---- input converts (independent of CSR) ----
    const int xn4 = NN * 128 / 4;
    k_cvt<<<(xn4 + 255) / 256, 256>>>((const float4*)x, (uint2*)xb, xn4);
    k_cvtW<<<(16384 + 255) / 256, 256>>>((const float4*)W1, (uint2*)W1b,
                                         (const float4*)W2, (uint2*)W2b,
                                         (const float4*)W3, (uint2*)W3b);

    // ---- CSR by dst ----
    k_zero_cnt<<<(NN + 255) / 256, 256>>>(cnt);
    k_histo<<<1024, 256>>>(dst, cnt, E);
    k_scan_part<<<NB, 1024>>>(cnt);
    k_scan_small<<<1, 1>>>(rowptr);
    k_scan_final<<<NB, 1024>>>(cnt, rowptr, cur);
    k_scatter<<<1024, 256>>>(src, dst, cur, csrc, E);

    dim3 gemm_grid(FD / BN, (NN + BM - 1) / BM);
    const int agg_grid = (NN + 3) / 4;

    // ---- layer 1 ----
    k_gemm_bf16<<<gemm_grid, 256, GEMM_SMEM>>>(xb, W1b, featb, al1, ar1, el, er, NN, 128);
    k_edge_agg<<<agg_grid, 128>>>((const uint4*)featb, (const float4*)el,
                                  (const float4*)er, rowptr, csrc, nullptr,
                                  (const float4*)b1, (float4*)hA, (uint4*)hinb);

    // ---- layer 2 ----
    k_gemm_bf16<<<gemm_grid, 256, GEMM_SMEM>>>(hinb, W2b, featb, al2, ar2, el, er, NN, FD);
    k_edge_agg<<<agg_grid, 128>>>((const uint4*)featb, (const float4*)el,
                                  (const float4*)er, rowptr, csrc,
                                  (const float4*)hA, (const float4*)b2, (float4*)hB,
                                  (uint4*)hinb);

    // ---- layer 3 ----
    k_gemm_bf16<<<gemm_grid, 256, GEMM_SMEM>>>(hinb, W3b, featb, al3, ar3, el, er, NN, FD);
    k_edge_agg<<<agg_grid, 128>>>((const uint4*)featb, (const float4*)el,
                                  (const float4*)er, rowptr, csrc,
                                  (const float4*)hB, (const float4*)b3, (float4*)hA,
                                  (uint4*)nullptr);

    // ---- layer 4 ----
    k_l4_proj<<<(NN + 7) / 8, 256>>>(hA, W4, resW4, al4, ar4, f4, r4, el, er);
    k_l4_edge<<<(NN + 7) / 8, 256>>>(f4, el, er, rowptr, csrc, r4, b4, out);
}